// round 8
// baseline (speedup 1.0000x reference)
#include <cuda_runtime.h>
#include <cstdint>

// Problem constants
#define BB 256
#define TT 256
#define DD 512
#define HH 8
#define HD 64
#define KDIM 512
#define KP2 (KDIM / 2)        // 256 k-pairs per row

// Scratch (device globals; no allocation allowed)
__device__ float g_q[BB * HH * TT * HD];       // [B,H,T,HD] fp32
__device__ float g_k[BB * HH * TT * HD];
__device__ float g_v[BB * HH * TT * HD];
__device__ uint2 g_xs[(size_t)BB * TT * KP2];  // x split {hi,lo} per k-pair
__device__ uint2 g_w1s[3 * DD * KP2];          // Wqkv split
__device__ uint2 g_w2s[DD * KP2];              // Wout split
__device__ uint2 g_att[(size_t)BB * TT * KP2]; // attention out, split

// ---------------------------------------------------------------------------
// helpers
// ---------------------------------------------------------------------------
__device__ __forceinline__ uint32_t smem_u32(const void* p) {
    uint32_t a;
    asm("{ .reg .u64 t; cvta.to.shared.u64 t, %1; cvt.u32.u64 %0, t; }"
        : "=r"(a) : "l"(p));
    return a;
}

__device__ __forceinline__ void cp_async16(uint32_t dst, const void* src) {
    asm volatile("cp.async.cg.shared.global [%0], [%1], 16;"
                 :: "r"(dst), "l"(src) : "memory");
}
#define CP_COMMIT() asm volatile("cp.async.commit_group;" ::: "memory")
#define CP_WAIT1()  asm volatile("cp.async.wait_group 1;" ::: "memory")

__device__ __forceinline__ void mma_bf16(float* c, const uint32_t* a, const uint32_t* b) {
    asm volatile(
        "mma.sync.aligned.m16n8k16.row.col.f32.bf16.bf16.f32 "
        "{%0,%1,%2,%3}, {%4,%5,%6,%7}, {%8,%9}, {%0,%1,%2,%3};"
        : "+f"(c[0]), "+f"(c[1]), "+f"(c[2]), "+f"(c[3])
        : "r"(a[0]), "r"(a[1]), "r"(a[2]), "r"(a[3]), "r"(b[0]), "r"(b[1]));
}

// split two fp32 (consecutive k) into packed bf16x2 hi and lo pairs
__device__ __forceinline__ void split_pair(float x0, float x1,
                                           uint32_t& hi, uint32_t& lo) {
    asm("cvt.rn.bf16x2.f32 %0, %1, %2;" : "=r"(hi) : "f"(x1), "f"(x0));
    float h0 = __uint_as_float(hi << 16);
    float h1 = __uint_as_float(hi & 0xffff0000u);
    asm("cvt.rn.bf16x2.f32 %0, %1, %2;" : "=r"(lo) : "f"(x1 - h1), "f"(x0 - h0));
}

// ---------------------------------------------------------------------------
// Splitter: fp32 -> interleaved {hi_pair, lo_pair} uint2 per k-pair
// ---------------------------------------------------------------------------
__global__ void __launch_bounds__(256) split_kernel(
    const float4* __restrict__ in, uint4* __restrict__ out, int n4)
{
    int i = blockIdx.x * 256 + threadIdx.x;
    if (i < n4) {
        float4 v = in[i];
        uint4 o;
        split_pair(v.x, v.y, o.x, o.y);
        split_pair(v.z, v.w, o.z, o.w);
        out[i] = o;
    }
}

// ---------------------------------------------------------------------------
// 3xBF16 tensor-core GEMM on pre-split data.
// C[128x128] = A[128xK] @ B[128xK]^T, A/B in split uint2-per-k-pair format.
// MODE 0: epilogue applies RoPE, scatters fp32 to g_q/g_k/g_v
// MODE 1: epilogue writes fp32 dst_out
// 512 threads = 16 warps (4m x 4n); warp tile 32x32; BK=32;
// 3-stage cp.async pipeline; smem row stride 20 uint2 (conflict-free).
// ---------------------------------------------------------------------------
#define RP2 20
#define TILE_U2 (128 * RP2)            // 2560 uint2 per matrix per stage
#define STG_U2  (2 * TILE_U2)
#define STAGES  3
#define SMEM_BYTES (STAGES * STG_U2 * 8)   // 122880

template <int MODE>
__global__ void __launch_bounds__(512) mma_gemm_kernel(
    const uint2* __restrict__ A,
    const uint2* __restrict__ B,
    const float* __restrict__ cosT,
    const float* __restrict__ sinT,
    float* __restrict__ dst_out)
{
    extern __shared__ uint2 sm2[];
    const uint32_t sb = smem_u32(sm2);

    const int tid  = threadIdx.x;
    const int wid  = tid >> 5;
    const int lane = tid & 31;
    const int g    = lane >> 2;
    const int q    = lane & 3;
    const int bm   = blockIdx.y * 128;
    const int bn   = blockIdx.x * 128;
    const int wm   = wid & 3;
    const int wn   = wid >> 2;

    const uint2* Ag = A + (size_t)bm * KP2;
    const uint2* Bg = B + (size_t)bn * KP2;

    float c[2][4][4];
#pragma unroll
    for (int mf = 0; mf < 2; mf++)
#pragma unroll
        for (int nf = 0; nf < 4; nf++)
#pragma unroll
            for (int r = 0; r < 4; r++) c[mf][nf][r] = 0.f;

    auto load_stage = [&](int s, int kt) {
        const uint32_t abase = sb + (uint32_t)s * STG_U2 * 8;
        const uint32_t bbase = abase + TILE_U2 * 8;
#pragma unroll
        for (int i = 0; i < 2; i++) {
            int e   = tid + i * 512;       // 0..1023: row(128) x chunk(8)
            int row = e >> 3;
            int c8  = e & 7;               // 16B chunk = 2 k-pairs
            uint32_t so = (uint32_t)(row * RP2 + c8 * 2) * 8;
            cp_async16(abase + so, Ag + (size_t)row * KP2 + kt * 16 + c8 * 2);
            cp_async16(bbase + so, Bg + (size_t)row * KP2 + kt * 16 + c8 * 2);
        }
    };

    load_stage(0, 0); CP_COMMIT();
    load_stage(1, 1); CP_COMMIT();

#pragma unroll 1
    for (int kt = 0; kt < 16; kt++) {
        CP_WAIT1();
        __syncthreads();

        const uint2* as = sm2 + (kt % STAGES) * STG_U2;
        const uint2* bs = as + TILE_U2;
#pragma unroll
        for (int s2 = 0; s2 < 2; s2++) {
            const int c0 = s2 * 8;
            uint32_t ah[2][4], al[2][4], bh[4][2], bl[4][2];
#pragma unroll
            for (int mf = 0; mf < 2; mf++) {
                int r0 = wm * 32 + mf * 16 + g;
                uint2 p0 = as[r0 * RP2 + c0 + q];
                uint2 p1 = as[(r0 + 8) * RP2 + c0 + q];
                uint2 p2 = as[r0 * RP2 + c0 + q + 4];
                uint2 p3 = as[(r0 + 8) * RP2 + c0 + q + 4];
                ah[mf][0] = p0.x; ah[mf][1] = p1.x; ah[mf][2] = p2.x; ah[mf][3] = p3.x;
                al[mf][0] = p0.y; al[mf][1] = p1.y; al[mf][2] = p2.y; al[mf][3] = p3.y;
            }
#pragma unroll
            for (int nf = 0; nf < 4; nf++) {
                int n0 = wn * 32 + nf * 8 + g;
                uint2 q0 = bs[n0 * RP2 + c0 + q];
                uint2 q1 = bs[n0 * RP2 + c0 + q + 4];
                bh[nf][0] = q0.x; bh[nf][1] = q1.x;
                bl[nf][0] = q0.y; bl[nf][1] = q1.y;
            }
#pragma unroll
            for (int mf = 0; mf < 2; mf++)
#pragma unroll
                for (int nf = 0; nf < 4; nf++) {
                    mma_bf16(c[mf][nf], ah[mf], bh[nf]);
                    mma_bf16(c[mf][nf], al[mf], bh[nf]);
                    mma_bf16(c[mf][nf], ah[mf], bl[nf]);
                }
        }

        __syncthreads();
        if (kt + 2 < 16) load_stage((kt + 2) % STAGES, kt + 2);
        CP_COMMIT();
    }

    // -------- epilogue (registers only) --------
#pragma unroll
    for (int mf = 0; mf < 2; mf++) {
#pragma unroll
        for (int rr = 0; rr < 2; rr++) {
            int m = bm + wm * 32 + mf * 16 + g + rr * 8;
#pragma unroll
            for (int nf = 0; nf < 4; nf++) {
                int n = bn + wn * 32 + nf * 8 + 2 * q;
                float v0 = c[mf][nf][rr * 2 + 0];
                float v1 = c[mf][nf][rr * 2 + 1];
                if (MODE == 0) {
                    int bI = m >> 8, t = m & 255;
                    int sec = n >> 9, h = (n >> 6) & 7, d = n & 63;
                    float* dst = (sec == 0) ? g_q : ((sec == 1) ? g_k : g_v);
                    if (sec < 2) {
                        float co = __ldg(cosT + t * HD + d);
                        float sn = __ldg(sinT + t * HD + d);
                        float t0 = v0 * co - v1 * sn;
                        float t1 = v1 * co + v0 * sn;
                        v0 = t0; v1 = t1;
                    }
                    *(float2*)(dst + ((((size_t)bI * HH + h) * TT + t) * HD + d)) =
                        make_float2(v0, v1);
                } else {
                    *(float2*)(dst_out + (size_t)m * DD + n) = make_float2(v0, v1);
                }
            }
        }
    }
}

// ---------------------------------------------------------------------------
// Kernel 2: causal flash attention (fp32 SIMT); epilogue writes split format.
// ---------------------------------------------------------------------------
__global__ void __launch_bounds__(256) attn_kernel()
{
    const int qt = blockIdx.x;
    const int bh = blockIdx.y;
    const float* Qg = g_q + ((size_t)bh * TT + qt * 64) * HD;
    const float* Kg = g_k + (size_t)bh * TT * HD;
    const float* Vg = g_v + (size_t)bh * TT * HD;

    __shared__ float Qs[64][64];
    __shared__ float KP[64][64];
    __shared__ float Vs[64][64];

    const int tid = threadIdx.x;
    const int ty = tid >> 4;
    const int tx = tid & 15;

#pragma unroll
    for (int l = 0; l < 4; l++) {
        int f = tid + l * 256;
        int r = f >> 4, c4 = f & 15;
        *(float4*)&Qs[r][c4 * 4] = *(const float4*)(Qg + r * HD + c4 * 4);
    }

    float O[4][4];
    float mrow[4], lrow[4];
#pragma unroll
    for (int i = 0; i < 4; i++) {
        mrow[i] = -3.0e38f;
        lrow[i] = 0.f;
#pragma unroll
        for (int j = 0; j < 4; j++) O[i][j] = 0.f;
    }

    const float scale = 0.125f;

    for (int kt = 0; kt <= qt; kt++) {
        __syncthreads();
#pragma unroll
        for (int l = 0; l < 4; l++) {
            int f = tid + l * 256;
            int r = f >> 4, c4 = f & 15;
            const float* kp = Kg + ((size_t)kt * 64 + r) * HD + c4 * 4;
            float4 kv = *(const float4*)kp;
            int d0 = c4 * 4;
            KP[r][(d0 + 0 + r) & 63] = kv.x;
            KP[r][(d0 + 1 + r) & 63] = kv.y;
            KP[r][(d0 + 2 + r) & 63] = kv.z;
            KP[r][(d0 + 3 + r) & 63] = kv.w;
            *(float4*)&Vs[r][c4 * 4] =
                *(const float4*)(Vg + ((size_t)kt * 64 + r) * HD + c4 * 4);
        }
        __syncthreads();

        float S[4][4];
#pragma unroll
        for (int i = 0; i < 4; i++)
#pragma unroll
            for (int j = 0; j < 4; j++) S[i][j] = 0.f;

#pragma unroll 8
        for (int d = 0; d < 64; d++) {
            float a[4], b[4];
#pragma unroll
            for (int i = 0; i < 4; i++) a[i] = Qs[ty * 4 + i][d];
#pragma unroll
            for (int j = 0; j < 4; j++) {
                int cc = tx * 4 + j;
                b[j] = KP[cc][(d + cc) & 63];
            }
#pragma unroll
            for (int i = 0; i < 4; i++)
#pragma unroll
                for (int j = 0; j < 4; j++) S[i][j] += a[i] * b[j];
        }

        if (kt == qt) {
#pragma unroll
            for (int i = 0; i < 4; i++)
#pragma unroll
                for (int j = 0; j < 4; j++) {
                    int qr = ty * 4 + i, kc = tx * 4 + j;
                    S[i][j] = (kc > qr) ? -3.0e38f : S[i][j] * scale;
                }
        } else {
#pragma unroll
            for (int i = 0; i < 4; i++)
#pragma unroll
                for (int j = 0; j < 4; j++) S[i][j] *= scale;
        }

#pragma unroll
        for (int i = 0; i < 4; i++) {
            float mloc = S[i][0];
#pragma unroll
            for (int j = 1; j < 4; j++) mloc = fmaxf(mloc, S[i][j]);
#pragma unroll
            for (int off = 8; off >= 1; off >>= 1)
                mloc = fmaxf(mloc, __shfl_xor_sync(0xffffffffu, mloc, off, 16));
            float mnew = fmaxf(mrow[i], mloc);
            float alpha = expf(mrow[i] - mnew);
            float psum = 0.f;
#pragma unroll
            for (int j = 0; j < 4; j++) {
                float p = expf(S[i][j] - mnew);
                S[i][j] = p;
                psum += p;
            }
#pragma unroll
            for (int off = 8; off >= 1; off >>= 1)
                psum += __shfl_xor_sync(0xffffffffu, psum, off, 16);
            lrow[i] = lrow[i] * alpha + psum;
            mrow[i] = mnew;
#pragma unroll
            for (int j = 0; j < 4; j++) O[i][j] *= alpha;
        }

        __syncthreads();
#pragma unroll
        for (int i = 0; i < 4; i++) {
            float4 p4 = make_float4(S[i][0], S[i][1], S[i][2], S[i][3]);
            *(float4*)&KP[ty * 4 + i][tx * 4] = p4;
        }
        __syncthreads();

#pragma unroll 8
        for (int cc = 0; cc < 64; cc++) {
            float p[4], vv[4];
#pragma unroll
            for (int i = 0; i < 4; i++) p[i] = KP[ty * 4 + i][cc];
#pragma unroll
            for (int j = 0; j < 4; j++) vv[j] = Vs[cc][tx * 4 + j];
#pragma unroll
            for (int i = 0; i < 4; i++)
#pragma unroll
                for (int j = 0; j < 4; j++) O[i][j] += p[i] * vv[j];
        }
    }

    // write split {hi,lo} pairs directly (consumed by out-proj GEMM)
    const int b = bh >> 3;
    const int h = bh & 7;
    const int col = h * HD + tx * 4;      // multiple of 4
#pragma unroll
    for (int i = 0; i < 4; i++) {
        float inv = 1.f / lrow[i];
        int t = qt * 64 + ty * 4 + i;
        float o0 = O[i][0] * inv, o1 = O[i][1] * inv;
        float o2 = O[i][2] * inv, o3 = O[i][3] * inv;
        uint4 w;
        split_pair(o0, o1, w.x, w.y);
        split_pair(o2, o3, w.z, w.w);
        *(uint4*)(g_att + ((size_t)b * TT + t) * KP2 + (col >> 1)) = w;
    }
}

// ---------------------------------------------------------------------------
extern "C" void kernel_launch(void* const* d_in, const int* in_sizes, int n_in,
                              void* d_out, int out_size)
{
    const float* x    = (const float*)d_in[0];
    const float* cosT = (const float*)d_in[1];
    const float* sinT = (const float*)d_in[2];
    const float* Wqkv = (const float*)d_in[3];
    const float* Wout = (const float*)d_in[4];
    float* out = (float*)d_out;

    cudaFuncSetAttribute(mma_gemm_kernel<0>,
                         cudaFuncAttributeMaxDynamicSharedMemorySize, SMEM_BYTES);
    cudaFuncSetAttribute(mma_gemm_kernel<1>,
                         cudaFuncAttributeMaxDynamicSharedMemorySize, SMEM_BYTES);

    uint2* xs  = nullptr; cudaGetSymbolAddress((void**)&xs,  g_xs);
    uint2* w1s = nullptr; cudaGetSymbolAddress((void**)&w1s, g_w1s);
    uint2* w2s = nullptr; cudaGetSymbolAddress((void**)&w2s, g_w2s);
    uint2* att = nullptr; cudaGetSymbolAddress((void**)&att, g_att);

    // split x, Wqkv, Wout
    {
        int n4 = (BB * TT * DD) / 4;                 // 8388608
        split_kernel<<<n4 / 256, 256>>>((const float4*)x, (uint4*)xs, n4);
        int w1 = (3 * DD * KDIM) / 4;                // 196608
        split_kernel<<<(w1 + 255) / 256, 256>>>((const float4*)Wqkv, (uint4*)w1s, w1);
        int w2 = (DD * KDIM) / 4;                    // 65536
        split_kernel<<<(w2 + 255) / 256, 256>>>((const float4*)Wout, (uint4*)w2s, w2);
    }

    dim3 g1(12, 512);   // N=1536, M=65536
    mma_gemm_kernel<0><<<g1, 512, SMEM_BYTES>>>(xs, w1s, cosT, sinT, nullptr);

    dim3 ga(4, BB * HH);
    attn_kernel<<<ga, 256>>>();

    dim3 g2(4, 512);    // N=512
    mma_gemm_kernel<1><<<g2, 512, SMEM_BYTES>>>(att, w2s, cosT, sinT, out);
}

// round 9
// speedup vs baseline: 1.0573x; 1.0573x over previous
#include <cuda_runtime.h>
#include <cstdint>

// Problem constants
#define BB 256
#define TT 256
#define DD 512
#define HH 8
#define HD 64
#define KDIM 512

// Scratch (device globals; no allocation allowed)
__device__ float g_q[BB * HH * TT * HD];       // [B,H,T,HD] fp32
__device__ float g_k[BB * HH * TT * HD];
__device__ float g_v[BB * HH * TT * HD];
// bf16 hi/lo planes, K-major rows of 512
__device__ uint16_t g_xh[(size_t)BB * TT * KDIM];
__device__ uint16_t g_xl[(size_t)BB * TT * KDIM];
__device__ uint16_t g_w1h[3 * DD * KDIM];
__device__ uint16_t g_w1l[3 * DD * KDIM];
__device__ uint16_t g_w2h[DD * KDIM];
__device__ uint16_t g_w2l[DD * KDIM];
__device__ uint16_t g_ah[(size_t)BB * TT * KDIM];
__device__ uint16_t g_al[(size_t)BB * TT * KDIM];

// ---------------------------------------------------------------------------
// helpers
// ---------------------------------------------------------------------------
__device__ __forceinline__ uint32_t smem_u32(const void* p) {
    uint32_t a;
    asm("{ .reg .u64 t; cvta.to.shared.u64 t, %1; cvt.u32.u64 %0, t; }"
        : "=r"(a) : "l"(p));
    return a;
}

__device__ __forceinline__ void cp_async16(uint32_t dst, const void* src) {
    asm volatile("cp.async.cg.shared.global [%0], [%1], 16;"
                 :: "r"(dst), "l"(src) : "memory");
}
#define CP_COMMIT() asm volatile("cp.async.commit_group;" ::: "memory")
#define CP_WAIT1()  asm volatile("cp.async.wait_group 1;" ::: "memory")

__device__ __forceinline__ void mma_bf16(float* c, const uint32_t* a, const uint32_t* b) {
    asm volatile(
        "mma.sync.aligned.m16n8k16.row.col.f32.bf16.bf16.f32 "
        "{%0,%1,%2,%3}, {%4,%5,%6,%7}, {%8,%9}, {%0,%1,%2,%3};"
        : "+f"(c[0]), "+f"(c[1]), "+f"(c[2]), "+f"(c[3])
        : "r"(a[0]), "r"(a[1]), "r"(a[2]), "r"(a[3]), "r"(b[0]), "r"(b[1]));
}

#define LDM4(r0, r1, r2, r3, addr) \
    asm volatile("ldmatrix.sync.aligned.m8n8.x4.shared.b16 {%0,%1,%2,%3}, [%4];" \
                 : "=r"(r0), "=r"(r1), "=r"(r2), "=r"(r3) : "r"(addr))

// split two fp32 (consecutive k) into packed bf16x2 hi and lo pairs
__device__ __forceinline__ void split_pair(float x0, float x1,
                                           uint32_t& hi, uint32_t& lo) {
    asm("cvt.rn.bf16x2.f32 %0, %1, %2;" : "=r"(hi) : "f"(x1), "f"(x0));
    float h0 = __uint_as_float(hi << 16);
    float h1 = __uint_as_float(hi & 0xffff0000u);
    asm("cvt.rn.bf16x2.f32 %0, %1, %2;" : "=r"(lo) : "f"(x1 - h1), "f"(x0 - h0));
}

// ---------------------------------------------------------------------------
// Splitter: fp32 -> two bf16 planes (hi, lo)
// ---------------------------------------------------------------------------
__global__ void __launch_bounds__(256) split_kernel(
    const float4* __restrict__ in,
    uint2* __restrict__ oh, uint2* __restrict__ ol, int n4)
{
    int i = blockIdx.x * 256 + threadIdx.x;
    if (i < n4) {
        float4 v = in[i];
        uint2 h, l;
        split_pair(v.x, v.y, h.x, l.x);
        split_pair(v.z, v.w, h.y, l.y);
        oh[i] = h;
        ol[i] = l;
    }
}

// ---------------------------------------------------------------------------
// 3xBF16 GEMM on pre-split planes, ldmatrix fragment loads.
// C[128x128] = A[128xK] @ B[128xK]^T
// MODE 0: epilogue RoPE + scatter fp32 to g_q/g_k/g_v ; MODE 1: fp32 dst_out
// 512 threads = 16 warps (4m x 4n); warp tile 32x32; BK=32; 3-stage cp.async.
// smem: 4 planes per stage (Ahi, Alo, Bhi, Blo), 128 rows x 80B (64B data+pad).
// ---------------------------------------------------------------------------
#define STRIDE_B 80
#define PLANE_B (128 * STRIDE_B)       // 10240
#define STG_B   (4 * PLANE_B)          // 40960
#define STAGES  3
#define SMEM_BYTES (STAGES * STG_B)    // 122880

template <int MODE>
__global__ void __launch_bounds__(512) mma_gemm_kernel(
    const uint16_t* __restrict__ Ah, const uint16_t* __restrict__ Al,
    const uint16_t* __restrict__ Bh, const uint16_t* __restrict__ Bl,
    const float* __restrict__ cosT,
    const float* __restrict__ sinT,
    float* __restrict__ dst_out)
{
    extern __shared__ char smc[];
    const uint32_t sb = smem_u32(smc);

    const int tid  = threadIdx.x;
    const int wid  = tid >> 5;
    const int lane = tid & 31;
    const int g    = lane >> 2;
    const int q    = lane & 3;
    const int bm   = blockIdx.y * 128;
    const int bn   = blockIdx.x * 128;
    const int wm   = wid & 3;
    const int wn   = wid >> 2;

    float c[2][4][4];
#pragma unroll
    for (int mf = 0; mf < 2; mf++)
#pragma unroll
        for (int nf = 0; nf < 4; nf++)
#pragma unroll
            for (int r = 0; r < 4; r++) c[mf][nf][r] = 0.f;

    // ldmatrix lane addresses (within a stage), computed once.
    // A x4 tile (16x16): lane -> row (lane&15), k-half (lane>>4)
    const uint32_t a_off =
        (uint32_t)(wm * 32 + (lane & 15)) * STRIDE_B + (lane >> 4) * 16;
    // B x4 covers two n8k16 tiles: lanes 0-7: n0-7 k0; 8-15: n0-7 k8;
    // 16-23: n8-15 k0; 24-31: n8-15 k8
    const uint32_t b_off =
        (uint32_t)(wn * 32 + (lane & 7) + ((lane >> 4) << 3)) * STRIDE_B +
        ((lane >> 3) & 1) * 16;

    // cp.async: 2048 16B chunks per stage; 4 per thread.
    // e = [pm(4)][row(128)][c(4)] ; pm: 0=Ahi 1=Alo 2=Bhi 3=Blo
    auto load_stage = [&](int s, int kt) {
        const uint32_t base = sb + (uint32_t)s * STG_B;
#pragma unroll
        for (int i = 0; i < 4; i++) {
            int e   = tid + i * 512;
            int cch = e & 3;
            int row = (e >> 2) & 127;
            int pm  = e >> 9;
            const uint16_t* src;
            if (pm == 0)      src = Ah + (size_t)(bm + row) * KDIM;
            else if (pm == 1) src = Al + (size_t)(bm + row) * KDIM;
            else if (pm == 2) src = Bh + (size_t)(bn + row) * KDIM;
            else              src = Bl + (size_t)(bn + row) * KDIM;
            cp_async16(base + pm * PLANE_B + row * STRIDE_B + cch * 16,
                       src + kt * 32 + cch * 8);
        }
    };

    load_stage(0, 0); CP_COMMIT();
    load_stage(1, 1); CP_COMMIT();

#pragma unroll 1
    for (int kt = 0; kt < 16; kt++) {
        CP_WAIT1();
        __syncthreads();

        const uint32_t st = sb + (uint32_t)(kt % STAGES) * STG_B;
        const uint32_t aH = st + a_off;
        const uint32_t aL = aH + PLANE_B;
        const uint32_t bH = st + 2 * PLANE_B + b_off;
        const uint32_t bL = bH + PLANE_B;

#pragma unroll
        for (int s2 = 0; s2 < 2; s2++) {
            const uint32_t ko = s2 * 32;   // k16 = 32 bytes
            uint32_t ah[2][4], al[2][4], bh[4][2], bl[4][2];
            LDM4(ah[0][0], ah[0][1], ah[0][2], ah[0][3], aH + ko);
            LDM4(ah[1][0], ah[1][1], ah[1][2], ah[1][3], aH + 16 * STRIDE_B + ko);
            LDM4(al[0][0], al[0][1], al[0][2], al[0][3], aL + ko);
            LDM4(al[1][0], al[1][1], al[1][2], al[1][3], aL + 16 * STRIDE_B + ko);
            LDM4(bh[0][0], bh[0][1], bh[1][0], bh[1][1], bH + ko);
            LDM4(bh[2][0], bh[2][1], bh[3][0], bh[3][1], bH + 16 * STRIDE_B + ko);
            LDM4(bl[0][0], bl[0][1], bl[1][0], bl[1][1], bL + ko);
            LDM4(bl[2][0], bl[2][1], bl[3][0], bl[3][1], bL + 16 * STRIDE_B + ko);
#pragma unroll
            for (int mf = 0; mf < 2; mf++)
#pragma unroll
                for (int nf = 0; nf < 4; nf++) {
                    mma_bf16(c[mf][nf], ah[mf], bh[nf]);
                    mma_bf16(c[mf][nf], al[mf], bh[nf]);
                    mma_bf16(c[mf][nf], ah[mf], bl[nf]);
                }
        }

        __syncthreads();
        if (kt + 2 < 16) load_stage((kt + 2) % STAGES, kt + 2);
        CP_COMMIT();
    }

    // -------- epilogue (registers only) --------
#pragma unroll
    for (int mf = 0; mf < 2; mf++) {
#pragma unroll
        for (int rr = 0; rr < 2; rr++) {
            int m = bm + wm * 32 + mf * 16 + g + rr * 8;
#pragma unroll
            for (int nf = 0; nf < 4; nf++) {
                int n = bn + wn * 32 + nf * 8 + 2 * q;
                float v0 = c[mf][nf][rr * 2 + 0];
                float v1 = c[mf][nf][rr * 2 + 1];
                if (MODE == 0) {
                    int bI = m >> 8, t = m & 255;
                    int sec = n >> 9, h = (n >> 6) & 7, d = n & 63;
                    float* dst = (sec == 0) ? g_q : ((sec == 1) ? g_k : g_v);
                    if (sec < 2) {
                        float co = __ldg(cosT + t * HD + d);
                        float sn = __ldg(sinT + t * HD + d);
                        float t0 = v0 * co - v1 * sn;
                        float t1 = v1 * co + v0 * sn;
                        v0 = t0; v1 = t1;
                    }
                    *(float2*)(dst + ((((size_t)bI * HH + h) * TT + t) * HD + d)) =
                        make_float2(v0, v1);
                } else {
                    *(float2*)(dst_out + (size_t)m * DD + n) = make_float2(v0, v1);
                }
            }
        }
    }
}

// ---------------------------------------------------------------------------
// Kernel 2: causal flash attention (fp32 SIMT); epilogue writes split planes.
// ---------------------------------------------------------------------------
__global__ void __launch_bounds__(256) attn_kernel()
{
    const int qt = blockIdx.x;
    const int bh = blockIdx.y;
    const float* Qg = g_q + ((size_t)bh * TT + qt * 64) * HD;
    const float* Kg = g_k + (size_t)bh * TT * HD;
    const float* Vg = g_v + (size_t)bh * TT * HD;

    __shared__ float Qs[64][64];
    __shared__ float KP[64][64];
    __shared__ float Vs[64][64];

    const int tid = threadIdx.x;
    const int ty = tid >> 4;
    const int tx = tid & 15;

#pragma unroll
    for (int l = 0; l < 4; l++) {
        int f = tid + l * 256;
        int r = f >> 4, c4 = f & 15;
        *(float4*)&Qs[r][c4 * 4] = *(const float4*)(Qg + r * HD + c4 * 4);
    }

    float O[4][4];
    float mrow[4], lrow[4];
#pragma unroll
    for (int i = 0; i < 4; i++) {
        mrow[i] = -3.0e38f;
        lrow[i] = 0.f;
#pragma unroll
        for (int j = 0; j < 4; j++) O[i][j] = 0.f;
    }

    const float scale = 0.125f;

    for (int kt = 0; kt <= qt; kt++) {
        __syncthreads();
#pragma unroll
        for (int l = 0; l < 4; l++) {
            int f = tid + l * 256;
            int r = f >> 4, c4 = f & 15;
            const float* kp = Kg + ((size_t)kt * 64 + r) * HD + c4 * 4;
            float4 kv = *(const float4*)kp;
            int d0 = c4 * 4;
            KP[r][(d0 + 0 + r) & 63] = kv.x;
            KP[r][(d0 + 1 + r) & 63] = kv.y;
            KP[r][(d0 + 2 + r) & 63] = kv.z;
            KP[r][(d0 + 3 + r) & 63] = kv.w;
            *(float4*)&Vs[r][c4 * 4] =
                *(const float4*)(Vg + ((size_t)kt * 64 + r) * HD + c4 * 4);
        }
        __syncthreads();

        float S[4][4];
#pragma unroll
        for (int i = 0; i < 4; i++)
#pragma unroll
            for (int j = 0; j < 4; j++) S[i][j] = 0.f;

#pragma unroll 8
        for (int d = 0; d < 64; d++) {
            float a[4], b[4];
#pragma unroll
            for (int i = 0; i < 4; i++) a[i] = Qs[ty * 4 + i][d];
#pragma unroll
            for (int j = 0; j < 4; j++) {
                int cc = tx * 4 + j;
                b[j] = KP[cc][(d + cc) & 63];
            }
#pragma unroll
            for (int i = 0; i < 4; i++)
#pragma unroll
                for (int j = 0; j < 4; j++) S[i][j] += a[i] * b[j];
        }

        if (kt == qt) {
#pragma unroll
            for (int i = 0; i < 4; i++)
#pragma unroll
                for (int j = 0; j < 4; j++) {
                    int qr = ty * 4 + i, kc = tx * 4 + j;
                    S[i][j] = (kc > qr) ? -3.0e38f : S[i][j] * scale;
                }
        } else {
#pragma unroll
            for (int i = 0; i < 4; i++)
#pragma unroll
                for (int j = 0; j < 4; j++) S[i][j] *= scale;
        }

#pragma unroll
        for (int i = 0; i < 4; i++) {
            float mloc = S[i][0];
#pragma unroll
            for (int j = 1; j < 4; j++) mloc = fmaxf(mloc, S[i][j]);
#pragma unroll
            for (int off = 8; off >= 1; off >>= 1)
                mloc = fmaxf(mloc, __shfl_xor_sync(0xffffffffu, mloc, off, 16));
            float mnew = fmaxf(mrow[i], mloc);
            float alpha = expf(mrow[i] - mnew);
            float psum = 0.f;
#pragma unroll
            for (int j = 0; j < 4; j++) {
                float p = expf(S[i][j] - mnew);
                S[i][j] = p;
                psum += p;
            }
#pragma unroll
            for (int off = 8; off >= 1; off >>= 1)
                psum += __shfl_xor_sync(0xffffffffu, psum, off, 16);
            lrow[i] = lrow[i] * alpha + psum;
            mrow[i] = mnew;
#pragma unroll
            for (int j = 0; j < 4; j++) O[i][j] *= alpha;
        }

        __syncthreads();
#pragma unroll
        for (int i = 0; i < 4; i++) {
            float4 p4 = make_float4(S[i][0], S[i][1], S[i][2], S[i][3]);
            *(float4*)&KP[ty * 4 + i][tx * 4] = p4;
        }
        __syncthreads();

#pragma unroll 8
        for (int cc = 0; cc < 64; cc++) {
            float p[4], vv[4];
#pragma unroll
            for (int i = 0; i < 4; i++) p[i] = KP[ty * 4 + i][cc];
#pragma unroll
            for (int j = 0; j < 4; j++) vv[j] = Vs[cc][tx * 4 + j];
#pragma unroll
            for (int i = 0; i < 4; i++)
#pragma unroll
                for (int j = 0; j < 4; j++) O[i][j] += p[i] * vv[j];
        }
    }

    // write hi/lo bf16 planes directly (consumed by out-proj GEMM)
    const int b = bh >> 3;
    const int h = bh & 7;
    const int col = h * HD + tx * 4;      // multiple of 4
#pragma unroll
    for (int i = 0; i < 4; i++) {
        float inv = 1.f / lrow[i];
        int t = qt * 64 + ty * 4 + i;
        float o0 = O[i][0] * inv, o1 = O[i][1] * inv;
        float o2 = O[i][2] * inv, o3 = O[i][3] * inv;
        uint32_t h01, l01, h23, l23;
        split_pair(o0, o1, h01, l01);
        split_pair(o2, o3, h23, l23);
        size_t rowm = (size_t)b * TT + t;
        *(uint2*)(g_ah + rowm * KDIM + col) = make_uint2(h01, h23);
        *(uint2*)(g_al + rowm * KDIM + col) = make_uint2(l01, l23);
    }
}

// ---------------------------------------------------------------------------
extern "C" void kernel_launch(void* const* d_in, const int* in_sizes, int n_in,
                              void* d_out, int out_size)
{
    const float* x    = (const float*)d_in[0];
    const float* cosT = (const float*)d_in[1];
    const float* sinT = (const float*)d_in[2];
    const float* Wqkv = (const float*)d_in[3];
    const float* Wout = (const float*)d_in[4];
    float* out = (float*)d_out;

    cudaFuncSetAttribute(mma_gemm_kernel<0>,
                         cudaFuncAttributeMaxDynamicSharedMemorySize, SMEM_BYTES);
    cudaFuncSetAttribute(mma_gemm_kernel<1>,
                         cudaFuncAttributeMaxDynamicSharedMemorySize, SMEM_BYTES);

    uint16_t *xh, *xl, *w1h, *w1l, *w2h, *w2l, *ah, *al;
    cudaGetSymbolAddress((void**)&xh,  g_xh);
    cudaGetSymbolAddress((void**)&xl,  g_xl);
    cudaGetSymbolAddress((void**)&w1h, g_w1h);
    cudaGetSymbolAddress((void**)&w1l, g_w1l);
    cudaGetSymbolAddress((void**)&w2h, g_w2h);
    cudaGetSymbolAddress((void**)&w2l, g_w2l);
    cudaGetSymbolAddress((void**)&ah,  g_ah);
    cudaGetSymbolAddress((void**)&al,  g_al);

    // split x, Wqkv, Wout into bf16 hi/lo planes
    {
        int n4 = (BB * TT * DD) / 4;                 // 8388608
        split_kernel<<<n4 / 256, 256>>>((const float4*)x, (uint2*)xh, (uint2*)xl, n4);
        int w1 = (3 * DD * KDIM) / 4;
        split_kernel<<<(w1 + 255) / 256, 256>>>((const float4*)Wqkv, (uint2*)w1h, (uint2*)w1l, w1);
        int w2 = (DD * KDIM) / 4;
        split_kernel<<<(w2 + 255) / 256, 256>>>((const float4*)Wout, (uint2*)w2h, (uint2*)w2l, w2);
    }

    dim3 g1(12, 512);   // N=1536, M=65536
    mma_gemm_kernel<0><<<g1, 512, SMEM_BYTES>>>(xh, xl, w1h, w1l, cosT, sinT, nullptr);

    dim3 ga(4, BB * HH);
    attn_kernel<<<ga, 256>>>();

    dim3 g2(4, 512);    // N=512
    mma_gemm_kernel<1><<<g2, 512, SMEM_BYTES>>>(ah, al, w2h, w2l, cosT, sinT, out);
}

// round 12
// speedup vs baseline: 1.5619x; 1.4772x over previous
#include <cuda_runtime.h>
#include <cstdint>

// Problem constants
#define BB 256
#define TT 256
#define DD 512
#define HH 8
#define HD 64
#define KDIM 512

// Scratch (device globals; no allocation allowed) — bf16 hi/lo planes
__device__ uint16_t g_xh[(size_t)BB * TT * KDIM];
__device__ uint16_t g_xl[(size_t)BB * TT * KDIM];
__device__ uint16_t g_w1h[3 * DD * KDIM];
__device__ uint16_t g_w1l[3 * DD * KDIM];
__device__ uint16_t g_w2h[DD * KDIM];
__device__ uint16_t g_w2l[DD * KDIM];
__device__ uint16_t g_qh[(size_t)BB * HH * TT * HD];  // [B,H,T,HD]
__device__ uint16_t g_ql[(size_t)BB * HH * TT * HD];
__device__ uint16_t g_kh[(size_t)BB * HH * TT * HD];
__device__ uint16_t g_kl[(size_t)BB * HH * TT * HD];
__device__ uint16_t g_vh[(size_t)BB * HH * TT * HD];
__device__ uint16_t g_vl[(size_t)BB * HH * TT * HD];
__device__ uint16_t g_ah[(size_t)BB * TT * KDIM];     // attn out [B*T, D]
__device__ uint16_t g_al[(size_t)BB * TT * KDIM];

// ---------------------------------------------------------------------------
// helpers
// ---------------------------------------------------------------------------
__device__ __forceinline__ uint32_t smem_u32(const void* p) {
    uint32_t a;
    asm("{ .reg .u64 t; cvta.to.shared.u64 t, %1; cvt.u32.u64 %0, t; }"
        : "=r"(a) : "l"(p));
    return a;
}

__device__ __forceinline__ void cp_async16(uint32_t dst, const void* src) {
    asm volatile("cp.async.cg.shared.global [%0], [%1], 16;"
                 :: "r"(dst), "l"(src) : "memory");
}
#define CP_COMMIT() asm volatile("cp.async.commit_group;" ::: "memory")
#define CP_WAIT1()  asm volatile("cp.async.wait_group 1;" ::: "memory")
#define CP_WAIT0()  asm volatile("cp.async.wait_group 0;" ::: "memory")

__device__ __forceinline__ void mma_bf16(float* c, const uint32_t* a, const uint32_t* b) {
    asm volatile(
        "mma.sync.aligned.m16n8k16.row.col.f32.bf16.bf16.f32 "
        "{%0,%1,%2,%3}, {%4,%5,%6,%7}, {%8,%9}, {%0,%1,%2,%3};"
        : "+f"(c[0]), "+f"(c[1]), "+f"(c[2]), "+f"(c[3])
        : "r"(a[0]), "r"(a[1]), "r"(a[2]), "r"(a[3]), "r"(b[0]), "r"(b[1]));
}

#define LDM4(r0, r1, r2, r3, addr) \
    asm volatile("ldmatrix.sync.aligned.m8n8.x4.shared.b16 {%0,%1,%2,%3}, [%4];" \
                 : "=r"(r0), "=r"(r1), "=r"(r2), "=r"(r3) : "r"(addr))
#define LDM4T(r0, r1, r2, r3, addr) \
    asm volatile("ldmatrix.sync.aligned.m8n8.x4.trans.shared.b16 {%0,%1,%2,%3}, [%4];" \
                 : "=r"(r0), "=r"(r1), "=r"(r2), "=r"(r3) : "r"(addr))

__device__ __forceinline__ float ex2f(float x) {
    float y;
    asm("ex2.approx.ftz.f32 %0, %1;" : "=f"(y) : "f"(x));
    return y;
}

// split two fp32 (consecutive) into packed bf16x2 hi and lo pairs
__device__ __forceinline__ void split_pair(float x0, float x1,
                                           uint32_t& hi, uint32_t& lo) {
    asm("cvt.rn.bf16x2.f32 %0, %1, %2;" : "=r"(hi) : "f"(x1), "f"(x0));
    float h0 = __uint_as_float(hi << 16);
    float h1 = __uint_as_float(hi & 0xffff0000u);
    asm("cvt.rn.bf16x2.f32 %0, %1, %2;" : "=r"(lo) : "f"(x1 - h1), "f"(x0 - h0));
}

// ---------------------------------------------------------------------------
// Splitter: fp32 -> two bf16 planes (hi, lo)
// ---------------------------------------------------------------------------
__global__ void __launch_bounds__(256) split_kernel(
    const float4* __restrict__ in,
    uint2* __restrict__ oh, uint2* __restrict__ ol, int n4)
{
    int i = blockIdx.x * 256 + threadIdx.x;
    if (i < n4) {
        float4 v = in[i];
        uint2 h, l;
        split_pair(v.x, v.y, h.x, l.x);
        split_pair(v.z, v.w, h.y, l.y);
        oh[i] = h;
        ol[i] = l;
    }
}

// ---------------------------------------------------------------------------
// 3xBF16 GEMM (proven core). MODE 0: RoPE + write split q/k/v planes.
// MODE 1: fp32 dst_out. 512 thr = 16 warps (4m x 4n); BK=32; 2-stage cp.async.
// ---------------------------------------------------------------------------
#define STRIDE_B 80
#define PLANE_B (128 * STRIDE_B)       // 10240
#define STG_B   (4 * PLANE_B)          // 40960
#define STAGES  2
#define SMEM_BYTES (STAGES * STG_B)    // 81920

template <int MODE>
__global__ void __launch_bounds__(512, 2) mma_gemm_kernel(
    const uint16_t* __restrict__ Ah, const uint16_t* __restrict__ Al,
    const uint16_t* __restrict__ Bh, const uint16_t* __restrict__ Bl,
    const float* __restrict__ cosT,
    const float* __restrict__ sinT,
    float* __restrict__ dst_out)
{
    extern __shared__ char smc[];
    const uint32_t sb = smem_u32(smc);

    const int tid  = threadIdx.x;
    const int wid  = tid >> 5;
    const int lane = tid & 31;
    const int g    = lane >> 2;
    const int q    = lane & 3;
    const int bm   = blockIdx.y * 128;
    const int bn   = blockIdx.x * 128;
    const int wm   = wid & 3;
    const int wn   = wid >> 2;

    float c[2][4][4];
#pragma unroll
    for (int mf = 0; mf < 2; mf++)
#pragma unroll
        for (int nf = 0; nf < 4; nf++)
#pragma unroll
            for (int r = 0; r < 4; r++) c[mf][nf][r] = 0.f;

    const uint32_t a_off =
        (uint32_t)(wm * 32 + (lane & 15)) * STRIDE_B + (lane >> 4) * 16;
    const uint32_t b_off =
        (uint32_t)(wn * 32 + (lane & 7) + ((lane >> 4) << 3)) * STRIDE_B +
        ((lane >> 3) & 1) * 16;

    auto load_stage = [&](int s, int kt) {
        const uint32_t base = sb + (uint32_t)s * STG_B;
#pragma unroll
        for (int i = 0; i < 4; i++) {
            int e   = tid + i * 512;
            int cch = e & 3;
            int row = (e >> 2) & 127;
            int pm  = e >> 9;
            const uint16_t* src;
            if (pm == 0)      src = Ah + (size_t)(bm + row) * KDIM;
            else if (pm == 1) src = Al + (size_t)(bm + row) * KDIM;
            else if (pm == 2) src = Bh + (size_t)(bn + row) * KDIM;
            else              src = Bl + (size_t)(bn + row) * KDIM;
            cp_async16(base + pm * PLANE_B + row * STRIDE_B + cch * 16,
                       src + kt * 32 + cch * 8);
        }
    };

    load_stage(0, 0); CP_COMMIT();
    load_stage(1, 1); CP_COMMIT();

#pragma unroll 1
    for (int kt = 0; kt < 16; kt++) {
        CP_WAIT1();
        __syncthreads();

        const uint32_t st = sb + (uint32_t)(kt % STAGES) * STG_B;
        const uint32_t aH = st + a_off;
        const uint32_t aL = aH + PLANE_B;
        const uint32_t bH = st + 2 * PLANE_B + b_off;
        const uint32_t bL = bH + PLANE_B;

#pragma unroll
        for (int s2 = 0; s2 < 2; s2++) {
            const uint32_t ko = s2 * 32;
            uint32_t ah[2][4], al[2][4], bh[4][2], bl[4][2];
            LDM4(ah[0][0], ah[0][1], ah[0][2], ah[0][3], aH + ko);
            LDM4(ah[1][0], ah[1][1], ah[1][2], ah[1][3], aH + 16 * STRIDE_B + ko);
            LDM4(al[0][0], al[0][1], al[0][2], al[0][3], aL + ko);
            LDM4(al[1][0], al[1][1], al[1][2], al[1][3], aL + 16 * STRIDE_B + ko);
            LDM4(bh[0][0], bh[0][1], bh[1][0], bh[1][1], bH + ko);
            LDM4(bh[2][0], bh[2][1], bh[3][0], bh[3][1], bH + 16 * STRIDE_B + ko);
            LDM4(bl[0][0], bl[0][1], bl[1][0], bl[1][1], bL + ko);
            LDM4(bl[2][0], bl[2][1], bl[3][0], bl[3][1], bL + 16 * STRIDE_B + ko);
#pragma unroll
            for (int mf = 0; mf < 2; mf++)
#pragma unroll
                for (int nf = 0; nf < 4; nf++) {
                    mma_bf16(c[mf][nf], ah[mf], bh[nf]);
                    mma_bf16(c[mf][nf], al[mf], bh[nf]);
                    mma_bf16(c[mf][nf], ah[mf], bl[nf]);
                }
        }

        __syncthreads();
        if (kt + 2 < 16) load_stage((kt + 2) % STAGES, kt + 2);
        CP_COMMIT();
    }

    // -------- epilogue --------
#pragma unroll
    for (int mf = 0; mf < 2; mf++) {
#pragma unroll
        for (int rr = 0; rr < 2; rr++) {
            int m = bm + wm * 32 + mf * 16 + g + rr * 8;
#pragma unroll
            for (int nf = 0; nf < 4; nf++) {
                int n = bn + wn * 32 + nf * 8 + 2 * q;
                float v0 = c[mf][nf][rr * 2 + 0];
                float v1 = c[mf][nf][rr * 2 + 1];
                if (MODE == 0) {
                    int bI = m >> 8, t = m & 255;
                    int sec = n >> 9, h = (n >> 6) & 7, d = n & 63;
                    if (sec < 2) {
                        float co = __ldg(cosT + t * HD + d);
                        float sn = __ldg(sinT + t * HD + d);
                        float t0 = v0 * co - v1 * sn;
                        float t1 = v1 * co + v0 * sn;
                        v0 = t0; v1 = t1;
                    }
                    uint16_t* dh = (sec == 0) ? g_qh : ((sec == 1) ? g_kh : g_vh);
                    uint16_t* dl = (sec == 0) ? g_ql : ((sec == 1) ? g_kl : g_vl);
                    size_t idx = (((size_t)bI * HH + h) * TT + t) * HD + d;
                    uint32_t hh, ll;
                    split_pair(v0, v1, hh, ll);
                    *(uint32_t*)(dh + idx) = hh;
                    *(uint32_t*)(dl + idx) = ll;
                } else {
                    *(float2*)(dst_out + (size_t)m * DD + n) = make_float2(v0, v1);
                }
            }
        }
    }
}

// ---------------------------------------------------------------------------
// Tensor-core causal flash attention (3xbf16).
// CTA = (qtile of 64 rows, bh). 128 threads = 4 warps; warp owns 16 q-rows
// (full row strip -> warp-local softmax). KV tiles of 64, double-buffered.
// Row = 64 bf16 = 128B data; stride 144B -> (addr/16)%8 = (9r+c)%8 conflict-free.
// ---------------------------------------------------------------------------
#define ASTRIDE 144
#define APLANE (64 * ASTRIDE)          // 9216
#define KV_STG (4 * APLANE)            // 36864
#define ATT_SMEM (2 * APLANE + 2 * KV_STG)  // 92160

__global__ void __launch_bounds__(128, 2) attn_mma_kernel()
{
    extern __shared__ char smc[];
    const uint32_t sb = smem_u32(smc);

    const int qt  = blockIdx.x;        // 0..3
    const int bh  = blockIdx.y;        // 0..2047
    const int tid = threadIdx.x;
    const int wid = tid >> 5;
    const int lane = tid & 31;
    const int g = lane >> 2;
    const int q = lane & 3;

    const size_t bhoff = (size_t)bh * TT * HD;
    const uint16_t* Qh = g_qh + bhoff + (size_t)qt * 64 * HD;
    const uint16_t* Ql = g_ql + bhoff + (size_t)qt * 64 * HD;
    const uint16_t* Kh = g_kh + bhoff;
    const uint16_t* Kl = g_kl + bhoff;
    const uint16_t* Vh = g_vh + bhoff;
    const uint16_t* Vl = g_vl + bhoff;

    // load Q planes: 2 planes x 64 rows x 8 chunks = 1024 chunks / 128 thr
#pragma unroll
    for (int i = 0; i < 8; i++) {
        int e = tid + i * 128;
        int pl = e >> 9;
        int row = (e >> 3) & 63;
        int ch = e & 7;
        const uint16_t* src = (pl ? Ql : Qh) + (size_t)row * HD + ch * 8;
        cp_async16(sb + pl * APLANE + row * ASTRIDE + ch * 16, src);
    }
    CP_COMMIT();

    auto load_kv = [&](int s, int kt) {
        const uint32_t base = sb + 2 * APLANE + (uint32_t)s * KV_STG;
#pragma unroll
        for (int i = 0; i < 16; i++) {
            int e = tid + i * 128;
            int pm = e >> 9;           // 0=Kh 1=Kl 2=Vh 3=Vl
            int row = (e >> 3) & 63;
            int ch = e & 7;
            const uint16_t* src =
                (pm == 0 ? Kh : pm == 1 ? Kl : pm == 2 ? Vh : Vl) +
                (size_t)(kt * 64 + row) * HD + ch * 8;
            cp_async16(base + pm * APLANE + row * ASTRIDE + ch * 16, src);
        }
    };
    load_kv(0, 0); CP_COMMIT();

    // wait Q (kv0 may still be in flight)
    CP_WAIT1();
    __syncthreads();

    // Q fragments (persist): 4 k-chunks x (hi,lo)
    uint32_t qfh[4][4], qfl[4][4];
    {
        const uint32_t qa = sb + (uint32_t)(wid * 16 + (lane & 15)) * ASTRIDE +
                            (lane >> 4) * 16;
#pragma unroll
        for (int kc = 0; kc < 4; kc++) {
            LDM4(qfh[kc][0], qfh[kc][1], qfh[kc][2], qfh[kc][3], qa + kc * 32);
            LDM4(qfl[kc][0], qfl[kc][1], qfl[kc][2], qfl[kc][3],
                 qa + APLANE + kc * 32);
        }
    }

    float O[8][4];
#pragma unroll
    for (int nf = 0; nf < 8; nf++)
#pragma unroll
        for (int j = 0; j < 4; j++) O[nf][j] = 0.f;
    float m2[2] = {-1e30f, -1e30f};
    float lsum[2] = {0.f, 0.f};
    const float sc2 = 0.125f * 1.44269504088896f;   // scale * log2(e)
    const int row0 = qt * 64 + wid * 16 + g;        // row for j=0,1; +8 for j=2,3

    const uint32_t kaddr_off =
        (uint32_t)((lane & 7) + ((lane >> 4) << 3)) * ASTRIDE +
        ((lane >> 3) & 1) * 16;
    const uint32_t vaddr_off =
        (uint32_t)(lane & 15) * ASTRIDE + (lane >> 4) * 16;

#pragma unroll 1
    for (int kt = 0; kt <= qt; kt++) {
        __syncthreads();               // prev compute done before overwrite
        if (kt < qt) {
            load_kv((kt + 1) & 1, kt + 1);
            CP_COMMIT();
            CP_WAIT1();
        } else {
            CP_WAIT0();
        }
        __syncthreads();

        const uint32_t kb = sb + 2 * APLANE + (uint32_t)(kt & 1) * KV_STG;

        // ---- S = Q @ K^T ----
        float s[8][4];
#pragma unroll
        for (int nf = 0; nf < 8; nf++)
#pragma unroll
            for (int j = 0; j < 4; j++) s[nf][j] = 0.f;

#pragma unroll
        for (int kc = 0; kc < 4; kc++) {
#pragma unroll
            for (int np = 0; np < 4; np++) {
                uint32_t kh[4], kl[4];
                const uint32_t ka = kb + kaddr_off + np * 16 * ASTRIDE + kc * 32;
                LDM4(kh[0], kh[1], kh[2], kh[3], ka);
                LDM4(kl[0], kl[1], kl[2], kl[3], ka + APLANE);
                mma_bf16(s[2 * np],     qfh[kc], kh);
                mma_bf16(s[2 * np],     qfl[kc], kh);
                mma_bf16(s[2 * np],     qfh[kc], kl);
                mma_bf16(s[2 * np + 1], qfh[kc], kh + 2);
                mma_bf16(s[2 * np + 1], qfl[kc], kh + 2);
                mma_bf16(s[2 * np + 1], qfh[kc], kl + 2);
            }
        }

        // ---- scale (base-2), mask, online softmax ----
        float mx0 = -1e30f, mx1 = -1e30f;
#pragma unroll
        for (int nf = 0; nf < 8; nf++) {
            int colb = kt * 64 + nf * 8 + 2 * q;
#pragma unroll
            for (int j = 0; j < 4; j++) {
                float v = s[nf][j] * sc2;
                if (kt == qt) {
                    int col = colb + (j & 1);
                    int row = row0 + ((j >> 1) << 3);
                    if (col > row) v = -1e30f;
                }
                s[nf][j] = v;
            }
            mx0 = fmaxf(mx0, fmaxf(s[nf][0], s[nf][1]));
            mx1 = fmaxf(mx1, fmaxf(s[nf][2], s[nf][3]));
        }
        mx0 = fmaxf(mx0, __shfl_xor_sync(0xffffffffu, mx0, 1));
        mx0 = fmaxf(mx0, __shfl_xor_sync(0xffffffffu, mx0, 2));
        mx1 = fmaxf(mx1, __shfl_xor_sync(0xffffffffu, mx1, 1));
        mx1 = fmaxf(mx1, __shfl_xor_sync(0xffffffffu, mx1, 2));
        float mn0 = fmaxf(m2[0], mx0), mn1 = fmaxf(m2[1], mx1);
        float a0 = ex2f(m2[0] - mn0), a1 = ex2f(m2[1] - mn1);
        m2[0] = mn0; m2[1] = mn1;
        float ls0 = 0.f, ls1 = 0.f;
#pragma unroll
        for (int nf = 0; nf < 8; nf++) {
            float p0 = ex2f(s[nf][0] - mn0);
            float p1 = ex2f(s[nf][1] - mn0);
            float p2 = ex2f(s[nf][2] - mn1);
            float p3 = ex2f(s[nf][3] - mn1);
            s[nf][0] = p0; s[nf][1] = p1; s[nf][2] = p2; s[nf][3] = p3;
            ls0 += p0 + p1; ls1 += p2 + p3;
            O[nf][0] *= a0; O[nf][1] *= a0;
            O[nf][2] *= a1; O[nf][3] *= a1;
        }
        lsum[0] = lsum[0] * a0 + ls0;
        lsum[1] = lsum[1] * a1 + ls1;

        // ---- O += P @ V  (P in regs; V^T via ldmatrix.trans) ----
#pragma unroll
        for (int kc = 0; kc < 4; kc++) {
            uint32_t ph[4], pl[4];
            split_pair(s[2 * kc][0],     s[2 * kc][1],     ph[0], pl[0]);
            split_pair(s[2 * kc][2],     s[2 * kc][3],     ph[1], pl[1]);
            split_pair(s[2 * kc + 1][0], s[2 * kc + 1][1], ph[2], pl[2]);
            split_pair(s[2 * kc + 1][2], s[2 * kc + 1][3], ph[3], pl[3]);
#pragma unroll
            for (int np = 0; np < 4; np++) {
                uint32_t vh[4], vl[4];
                const uint32_t va = kb + 2 * APLANE + vaddr_off +
                                    kc * 16 * ASTRIDE + np * 32;
                LDM4T(vh[0], vh[1], vh[2], vh[3], va);
                LDM4T(vl[0], vl[1], vl[2], vl[3], va + APLANE);
                mma_bf16(O[2 * np],     ph, vh);
                mma_bf16(O[2 * np],     pl, vh);
                mma_bf16(O[2 * np],     ph, vl);
                mma_bf16(O[2 * np + 1], ph, vh + 2);
                mma_bf16(O[2 * np + 1], pl, vh + 2);
                mma_bf16(O[2 * np + 1], ph, vl + 2);
            }
        }
    }

    // final normalize + write split planes for out-proj
    float l0 = lsum[0];
    l0 += __shfl_xor_sync(0xffffffffu, l0, 1);
    l0 += __shfl_xor_sync(0xffffffffu, l0, 2);
    float l1 = lsum[1];
    l1 += __shfl_xor_sync(0xffffffffu, l1, 1);
    l1 += __shfl_xor_sync(0xffffffffu, l1, 2);
    const float inv0 = 1.f / l0, inv1 = 1.f / l1;

    const int b = bh >> 3;
    const int h = bh & 7;
    const int t0 = qt * 64 + wid * 16 + g;
    const size_t r0 = (size_t)b * TT + t0;
    const size_t r1 = r0 + 8;
#pragma unroll
    for (int nf = 0; nf < 8; nf++) {
        int col = h * HD + nf * 8 + 2 * q;
        uint32_t hh, ll;
        split_pair(O[nf][0] * inv0, O[nf][1] * inv0, hh, ll);
        *(uint32_t*)(g_ah + r0 * KDIM + col) = hh;
        *(uint32_t*)(g_al + r0 * KDIM + col) = ll;
        split_pair(O[nf][2] * inv1, O[nf][3] * inv1, hh, ll);
        *(uint32_t*)(g_ah + r1 * KDIM + col) = hh;
        *(uint32_t*)(g_al + r1 * KDIM + col) = ll;
    }
}

// ---------------------------------------------------------------------------
extern "C" void kernel_launch(void* const* d_in, const int* in_sizes, int n_in,
                              void* d_out, int out_size)
{
    const float* x    = (const float*)d_in[0];
    const float* cosT = (const float*)d_in[1];
    const float* sinT = (const float*)d_in[2];
    const float* Wqkv = (const float*)d_in[3];
    const float* Wout = (const float*)d_in[4];
    float* out = (float*)d_out;

    cudaFuncSetAttribute(mma_gemm_kernel<0>,
                         cudaFuncAttributeMaxDynamicSharedMemorySize, SMEM_BYTES);
    cudaFuncSetAttribute(mma_gemm_kernel<1>,
                         cudaFuncAttributeMaxDynamicSharedMemorySize, SMEM_BYTES);
    cudaFuncSetAttribute(attn_mma_kernel,
                         cudaFuncAttributeMaxDynamicSharedMemorySize, ATT_SMEM);

    uint16_t *xh, *xl, *w1h, *w1l, *w2h, *w2l, *ah, *al;
    cudaGetSymbolAddress((void**)&xh,  g_xh);
    cudaGetSymbolAddress((void**)&xl,  g_xl);
    cudaGetSymbolAddress((void**)&w1h, g_w1h);
    cudaGetSymbolAddress((void**)&w1l, g_w1l);
    cudaGetSymbolAddress((void**)&w2h, g_w2h);
    cudaGetSymbolAddress((void**)&w2l, g_w2l);
    cudaGetSymbolAddress((void**)&ah,  g_ah);
    cudaGetSymbolAddress((void**)&al,  g_al);

    {
        int n4 = (BB * TT * DD) / 4;
        split_kernel<<<n4 / 256, 256>>>((const float4*)x, (uint2*)xh, (uint2*)xl, n4);
        int w1 = (3 * DD * KDIM) / 4;
        split_kernel<<<(w1 + 255) / 256, 256>>>((const float4*)Wqkv, (uint2*)w1h, (uint2*)w1l, w1);
        int w2 = (DD * KDIM) / 4;
        split_kernel<<<(w2 + 255) / 256, 256>>>((const float4*)Wout, (uint2*)w2h, (uint2*)w2l, w2);
    }

    dim3 g1(12, 512);   // N=1536, M=65536
    mma_gemm_kernel<0><<<g1, 512, SMEM_BYTES>>>(xh, xl, w1h, w1l, cosT, sinT, nullptr);

    dim3 ga(4, BB * HH);
    attn_mma_kernel<<<ga, 128, ATT_SMEM>>>();

    dim3 g2(4, 512);    // N=512
    mma_gemm_kernel<1><<<g2, 512, SMEM_BYTES>>>(ah, al, w2h, w2l, cosT, sinT, out);
}

// round 13
// speedup vs baseline: 1.6623x; 1.0642x over previous
#include <cuda_runtime.h>
#include <cstdint>

// Problem constants
#define BB 256
#define TT 256
#define DD 512
#define HH 8
#define HD 64
#define KDIM 512

// Scratch (device globals; no allocation allowed) — bf16 hi/lo planes
__device__ uint16_t g_xh[(size_t)BB * TT * KDIM];
__device__ uint16_t g_xl[(size_t)BB * TT * KDIM];
__device__ uint16_t g_w1h[3 * DD * KDIM];
__device__ uint16_t g_w1l[3 * DD * KDIM];
__device__ uint16_t g_w2h[DD * KDIM];
__device__ uint16_t g_w2l[DD * KDIM];
__device__ uint16_t g_qh[(size_t)BB * HH * TT * HD];  // [B,H,T,HD]
__device__ uint16_t g_ql[(size_t)BB * HH * TT * HD];
__device__ uint16_t g_kh[(size_t)BB * HH * TT * HD];
__device__ uint16_t g_kl[(size_t)BB * HH * TT * HD];
__device__ uint16_t g_vh[(size_t)BB * HH * TT * HD];
__device__ uint16_t g_vl[(size_t)BB * HH * TT * HD];
__device__ uint16_t g_ah[(size_t)BB * TT * KDIM];     // attn out [B*T, D]
__device__ uint16_t g_al[(size_t)BB * TT * KDIM];

// ---------------------------------------------------------------------------
// helpers
// ---------------------------------------------------------------------------
__device__ __forceinline__ uint32_t smem_u32(const void* p) {
    uint32_t a;
    asm("{ .reg .u64 t; cvta.to.shared.u64 t, %1; cvt.u32.u64 %0, t; }"
        : "=r"(a) : "l"(p));
    return a;
}

__device__ __forceinline__ void cp_async16(uint32_t dst, const void* src) {
    asm volatile("cp.async.cg.shared.global [%0], [%1], 16;"
                 :: "r"(dst), "l"(src) : "memory");
}
#define CP_COMMIT() asm volatile("cp.async.commit_group;" ::: "memory")
#define CP_WAIT1()  asm volatile("cp.async.wait_group 1;" ::: "memory")
#define CP_WAIT0()  asm volatile("cp.async.wait_group 0;" ::: "memory")

__device__ __forceinline__ void mma_bf16(float* c, const uint32_t* a, const uint32_t* b) {
    asm volatile(
        "mma.sync.aligned.m16n8k16.row.col.f32.bf16.bf16.f32 "
        "{%0,%1,%2,%3}, {%4,%5,%6,%7}, {%8,%9}, {%0,%1,%2,%3};"
        : "+f"(c[0]), "+f"(c[1]), "+f"(c[2]), "+f"(c[3])
        : "r"(a[0]), "r"(a[1]), "r"(a[2]), "r"(a[3]), "r"(b[0]), "r"(b[1]));
}

#define LDM4(r0, r1, r2, r3, addr) \
    asm volatile("ldmatrix.sync.aligned.m8n8.x4.shared.b16 {%0,%1,%2,%3}, [%4];" \
                 : "=r"(r0), "=r"(r1), "=r"(r2), "=r"(r3) : "r"(addr))
#define LDM4T(r0, r1, r2, r3, addr) \
    asm volatile("ldmatrix.sync.aligned.m8n8.x4.trans.shared.b16 {%0,%1,%2,%3}, [%4];" \
                 : "=r"(r0), "=r"(r1), "=r"(r2), "=r"(r3) : "r"(addr))

__device__ __forceinline__ float ex2f(float x) {
    float y;
    asm("ex2.approx.ftz.f32 %0, %1;" : "=f"(y) : "f"(x));
    return y;
}

// split two fp32 (consecutive) into packed bf16x2 hi and lo pairs
__device__ __forceinline__ void split_pair(float x0, float x1,
                                           uint32_t& hi, uint32_t& lo) {
    asm("cvt.rn.bf16x2.f32 %0, %1, %2;" : "=r"(hi) : "f"(x1), "f"(x0));
    float h0 = __uint_as_float(hi << 16);
    float h1 = __uint_as_float(hi & 0xffff0000u);
    asm("cvt.rn.bf16x2.f32 %0, %1, %2;" : "=r"(lo) : "f"(x1 - h1), "f"(x0 - h0));
}

// ---------------------------------------------------------------------------
// Splitter: fp32 -> two bf16 planes (hi, lo)
// ---------------------------------------------------------------------------
__global__ void __launch_bounds__(256) split_kernel(
    const float4* __restrict__ in,
    uint2* __restrict__ oh, uint2* __restrict__ ol, int n4)
{
    int i = blockIdx.x * 256 + threadIdx.x;
    if (i < n4) {
        float4 v = in[i];
        uint2 h, l;
        split_pair(v.x, v.y, h.x, l.x);
        split_pair(v.z, v.w, h.y, l.y);
        oh[i] = h;
        ol[i] = l;
    }
}

// ---------------------------------------------------------------------------
// 3xBF16 GEMM. MODE 0: RoPE + write split q/k/v planes. MODE 1: fp32 dst_out.
// 256 thr = 8 warps (2m x 4n); warp tile 64x32; CTA 128x128; BK=32; 2-stage.
// Per k16: B-frags loaded once (4 LDM4), A-frags streamed per mf (2 LDM4)
// -> 12 LDM4 / 48 mma = 128 B/mma smem traffic (was 170).
// ---------------------------------------------------------------------------
#define STRIDE_B 80
#define PLANE_B (128 * STRIDE_B)       // 10240
#define STG_B   (4 * PLANE_B)          // 40960
#define SMEM_BYTES (2 * STG_B)         // 81920

template <int MODE>
__global__ void __launch_bounds__(256, 2) mma_gemm_kernel(
    const uint16_t* __restrict__ Ah, const uint16_t* __restrict__ Al,
    const uint16_t* __restrict__ Bh, const uint16_t* __restrict__ Bl,
    const float* __restrict__ cosT,
    const float* __restrict__ sinT,
    float* __restrict__ dst_out)
{
    extern __shared__ char smc[];
    const uint32_t sb = smem_u32(smc);

    const int tid  = threadIdx.x;
    const int wid  = tid >> 5;      // 0..7
    const int lane = tid & 31;
    const int g    = lane >> 2;
    const int q    = lane & 3;
    const int bm   = blockIdx.y * 128;
    const int bn   = blockIdx.x * 128;
    const int wm   = wid & 1;       // 2 m-warps
    const int wn   = wid >> 1;      // 4 n-warps

    float c[4][4][4];
#pragma unroll
    for (int mf = 0; mf < 4; mf++)
#pragma unroll
        for (int nf = 0; nf < 4; nf++)
#pragma unroll
            for (int r = 0; r < 4; r++) c[mf][nf][r] = 0.f;

    const uint32_t a_off =
        (uint32_t)(wm * 64 + (lane & 15)) * STRIDE_B + (lane >> 4) * 16;
    const uint32_t b_off =
        (uint32_t)(wn * 32 + (lane & 7) + ((lane >> 4) << 3)) * STRIDE_B +
        ((lane >> 3) & 1) * 16;

    // 2048 16B chunks per stage / 256 threads = 8 each
    auto load_stage = [&](int s, int kt) {
        const uint32_t base = sb + (uint32_t)s * STG_B;
#pragma unroll
        for (int i = 0; i < 8; i++) {
            int e   = tid + i * 256;
            int cch = e & 3;
            int row = (e >> 2) & 127;
            int pm  = e >> 9;
            const uint16_t* src;
            if (pm == 0)      src = Ah + (size_t)(bm + row) * KDIM;
            else if (pm == 1) src = Al + (size_t)(bm + row) * KDIM;
            else if (pm == 2) src = Bh + (size_t)(bn + row) * KDIM;
            else              src = Bl + (size_t)(bn + row) * KDIM;
            cp_async16(base + pm * PLANE_B + row * STRIDE_B + cch * 16,
                       src + kt * 32 + cch * 8);
        }
    };

    load_stage(0, 0); CP_COMMIT();
    load_stage(1, 1); CP_COMMIT();

#pragma unroll 1
    for (int kt = 0; kt < 16; kt++) {
        CP_WAIT1();
        __syncthreads();

        const uint32_t st = sb + (uint32_t)(kt & 1) * STG_B;
        const uint32_t aH = st + a_off;
        const uint32_t aL = aH + PLANE_B;
        const uint32_t bH = st + 2 * PLANE_B + b_off;
        const uint32_t bL = bH + PLANE_B;

#pragma unroll
        for (int s2 = 0; s2 < 2; s2++) {
            const uint32_t ko = s2 * 32;
            uint32_t bh[4][2], bl[4][2];
            LDM4(bh[0][0], bh[0][1], bh[1][0], bh[1][1], bH + ko);
            LDM4(bh[2][0], bh[2][1], bh[3][0], bh[3][1], bH + 16 * STRIDE_B + ko);
            LDM4(bl[0][0], bl[0][1], bl[1][0], bl[1][1], bL + ko);
            LDM4(bl[2][0], bl[2][1], bl[3][0], bl[3][1], bL + 16 * STRIDE_B + ko);
#pragma unroll
            for (int mf = 0; mf < 4; mf++) {
                uint32_t ah[4], al[4];
                LDM4(ah[0], ah[1], ah[2], ah[3], aH + mf * 16 * STRIDE_B + ko);
                LDM4(al[0], al[1], al[2], al[3], aL + mf * 16 * STRIDE_B + ko);
#pragma unroll
                for (int nf = 0; nf < 4; nf++) {
                    mma_bf16(c[mf][nf], ah, bh[nf]);
                    mma_bf16(c[mf][nf], al, bh[nf]);
                    mma_bf16(c[mf][nf], ah, bl[nf]);
                }
            }
        }

        __syncthreads();
        if (kt + 2 < 16) load_stage(kt & 1, kt + 2);
        CP_COMMIT();
    }

    // -------- epilogue --------
#pragma unroll
    for (int mf = 0; mf < 4; mf++) {
#pragma unroll
        for (int rr = 0; rr < 2; rr++) {
            int m = bm + wm * 64 + mf * 16 + g + rr * 8;
#pragma unroll
            for (int nf = 0; nf < 4; nf++) {
                int n = bn + wn * 32 + nf * 8 + 2 * q;
                float v0 = c[mf][nf][rr * 2 + 0];
                float v1 = c[mf][nf][rr * 2 + 1];
                if (MODE == 0) {
                    int bI = m >> 8, t = m & 255;
                    int sec = n >> 9, h = (n >> 6) & 7, d = n & 63;
                    if (sec < 2) {
                        float co = __ldg(cosT + t * HD + d);
                        float sn = __ldg(sinT + t * HD + d);
                        float t0 = v0 * co - v1 * sn;
                        float t1 = v1 * co + v0 * sn;
                        v0 = t0; v1 = t1;
                    }
                    uint16_t* dh = (sec == 0) ? g_qh : ((sec == 1) ? g_kh : g_vh);
                    uint16_t* dl = (sec == 0) ? g_ql : ((sec == 1) ? g_kl : g_vl);
                    size_t idx = (((size_t)bI * HH + h) * TT + t) * HD + d;
                    uint32_t hh, ll;
                    split_pair(v0, v1, hh, ll);
                    *(uint32_t*)(dh + idx) = hh;
                    *(uint32_t*)(dl + idx) = ll;
                } else {
                    *(float2*)(dst_out + (size_t)m * DD + n) = make_float2(v0, v1);
                }
            }
        }
    }
}

// ---------------------------------------------------------------------------
// Tensor-core causal flash attention (3xbf16) — unchanged from R12 (proven).
// ---------------------------------------------------------------------------
#define ASTRIDE 144
#define APLANE (64 * ASTRIDE)          // 9216
#define KV_STG (4 * APLANE)            // 36864
#define ATT_SMEM (2 * APLANE + 2 * KV_STG)  // 92160

__global__ void __launch_bounds__(128, 2) attn_mma_kernel()
{
    extern __shared__ char smc[];
    const uint32_t sb = smem_u32(smc);

    const int qt  = blockIdx.x;        // 0..3
    const int bh  = blockIdx.y;        // 0..2047
    const int tid = threadIdx.x;
    const int wid = tid >> 5;
    const int lane = tid & 31;
    const int g = lane >> 2;
    const int q = lane & 3;

    const size_t bhoff = (size_t)bh * TT * HD;
    const uint16_t* Qh = g_qh + bhoff + (size_t)qt * 64 * HD;
    const uint16_t* Ql = g_ql + bhoff + (size_t)qt * 64 * HD;
    const uint16_t* Kh = g_kh + bhoff;
    const uint16_t* Kl = g_kl + bhoff;
    const uint16_t* Vh = g_vh + bhoff;
    const uint16_t* Vl = g_vl + bhoff;

#pragma unroll
    for (int i = 0; i < 8; i++) {
        int e = tid + i * 128;
        int pl = e >> 9;
        int row = (e >> 3) & 63;
        int ch = e & 7;
        const uint16_t* src = (pl ? Ql : Qh) + (size_t)row * HD + ch * 8;
        cp_async16(sb + pl * APLANE + row * ASTRIDE + ch * 16, src);
    }
    CP_COMMIT();

    auto load_kv = [&](int s, int kt) {
        const uint32_t base = sb + 2 * APLANE + (uint32_t)s * KV_STG;
#pragma unroll
        for (int i = 0; i < 16; i++) {
            int e = tid + i * 128;
            int pm = e >> 9;           // 0=Kh 1=Kl 2=Vh 3=Vl
            int row = (e >> 3) & 63;
            int ch = e & 7;
            const uint16_t* src =
                (pm == 0 ? Kh : pm == 1 ? Kl : pm == 2 ? Vh : Vl) +
                (size_t)(kt * 64 + row) * HD + ch * 8;
            cp_async16(base + pm * APLANE + row * ASTRIDE + ch * 16, src);
        }
    };
    load_kv(0, 0); CP_COMMIT();

    CP_WAIT1();
    __syncthreads();

    uint32_t qfh[4][4], qfl[4][4];
    {
        const uint32_t qa = sb + (uint32_t)(wid * 16 + (lane & 15)) * ASTRIDE +
                            (lane >> 4) * 16;
#pragma unroll
        for (int kc = 0; kc < 4; kc++) {
            LDM4(qfh[kc][0], qfh[kc][1], qfh[kc][2], qfh[kc][3], qa + kc * 32);
            LDM4(qfl[kc][0], qfl[kc][1], qfl[kc][2], qfl[kc][3],
                 qa + APLANE + kc * 32);
        }
    }

    float O[8][4];
#pragma unroll
    for (int nf = 0; nf < 8; nf++)
#pragma unroll
        for (int j = 0; j < 4; j++) O[nf][j] = 0.f;
    float m2[2] = {-1e30f, -1e30f};
    float lsum[2] = {0.f, 0.f};
    const float sc2 = 0.125f * 1.44269504088896f;   // scale * log2(e)
    const int row0 = qt * 64 + wid * 16 + g;

    const uint32_t kaddr_off =
        (uint32_t)((lane & 7) + ((lane >> 4) << 3)) * ASTRIDE +
        ((lane >> 3) & 1) * 16;
    const uint32_t vaddr_off =
        (uint32_t)(lane & 15) * ASTRIDE + (lane >> 4) * 16;

#pragma unroll 1
    for (int kt = 0; kt <= qt; kt++) {
        __syncthreads();
        if (kt < qt) {
            load_kv((kt + 1) & 1, kt + 1);
            CP_COMMIT();
            CP_WAIT1();
        } else {
            CP_WAIT0();
        }
        __syncthreads();

        const uint32_t kb = sb + 2 * APLANE + (uint32_t)(kt & 1) * KV_STG;

        float s[8][4];
#pragma unroll
        for (int nf = 0; nf < 8; nf++)
#pragma unroll
            for (int j = 0; j < 4; j++) s[nf][j] = 0.f;

#pragma unroll
        for (int kc = 0; kc < 4; kc++) {
#pragma unroll
            for (int np = 0; np < 4; np++) {
                uint32_t kh[4], kl[4];
                const uint32_t ka = kb + kaddr_off + np * 16 * ASTRIDE + kc * 32;
                LDM4(kh[0], kh[1], kh[2], kh[3], ka);
                LDM4(kl[0], kl[1], kl[2], kl[3], ka + APLANE);
                mma_bf16(s[2 * np],     qfh[kc], kh);
                mma_bf16(s[2 * np],     qfl[kc], kh);
                mma_bf16(s[2 * np],     qfh[kc], kl);
                mma_bf16(s[2 * np + 1], qfh[kc], kh + 2);
                mma_bf16(s[2 * np + 1], qfl[kc], kh + 2);
                mma_bf16(s[2 * np + 1], qfh[kc], kl + 2);
            }
        }

        float mx0 = -1e30f, mx1 = -1e30f;
#pragma unroll
        for (int nf = 0; nf < 8; nf++) {
            int colb = kt * 64 + nf * 8 + 2 * q;
#pragma unroll
            for (int j = 0; j < 4; j++) {
                float v = s[nf][j] * sc2;
                if (kt == qt) {
                    int col = colb + (j & 1);
                    int row = row0 + ((j >> 1) << 3);
                    if (col > row) v = -1e30f;
                }
                s[nf][j] = v;
            }
            mx0 = fmaxf(mx0, fmaxf(s[nf][0], s[nf][1]));
            mx1 = fmaxf(mx1, fmaxf(s[nf][2], s[nf][3]));
        }
        mx0 = fmaxf(mx0, __shfl_xor_sync(0xffffffffu, mx0, 1));
        mx0 = fmaxf(mx0, __shfl_xor_sync(0xffffffffu, mx0, 2));
        mx1 = fmaxf(mx1, __shfl_xor_sync(0xffffffffu, mx1, 1));
        mx1 = fmaxf(mx1, __shfl_xor_sync(0xffffffffu, mx1, 2));
        float mn0 = fmaxf(m2[0], mx0), mn1 = fmaxf(m2[1], mx1);
        float a0 = ex2f(m2[0] - mn0), a1 = ex2f(m2[1] - mn1);
        m2[0] = mn0; m2[1] = mn1;
        float ls0 = 0.f, ls1 = 0.f;
#pragma unroll
        for (int nf = 0; nf < 8; nf++) {
            float p0 = ex2f(s[nf][0] - mn0);
            float p1 = ex2f(s[nf][1] - mn0);
            float p2 = ex2f(s[nf][2] - mn1);
            float p3 = ex2f(s[nf][3] - mn1);
            s[nf][0] = p0; s[nf][1] = p1; s[nf][2] = p2; s[nf][3] = p3;
            ls0 += p0 + p1; ls1 += p2 + p3;
            O[nf][0] *= a0; O[nf][1] *= a0;
            O[nf][2] *= a1; O[nf][3] *= a1;
        }
        lsum[0] = lsum[0] * a0 + ls0;
        lsum[1] = lsum[1] * a1 + ls1;

#pragma unroll
        for (int kc = 0; kc < 4; kc++) {
            uint32_t ph[4], pl[4];
            split_pair(s[2 * kc][0],     s[2 * kc][1],     ph[0], pl[0]);
            split_pair(s[2 * kc][2],     s[2 * kc][3],     ph[1], pl[1]);
            split_pair(s[2 * kc + 1][0], s[2 * kc + 1][1], ph[2], pl[2]);
            split_pair(s[2 * kc + 1][2], s[2 * kc + 1][3], ph[3], pl[3]);
#pragma unroll
            for (int np = 0; np < 4; np++) {
                uint32_t vh[4], vl[4];
                const uint32_t va = kb + 2 * APLANE + vaddr_off +
                                    kc * 16 * ASTRIDE + np * 32;
                LDM4T(vh[0], vh[1], vh[2], vh[3], va);
                LDM4T(vl[0], vl[1], vl[2], vl[3], va + APLANE);
                mma_bf16(O[2 * np],     ph, vh);
                mma_bf16(O[2 * np],     pl, vh);
                mma_bf16(O[2 * np],     ph, vl);
                mma_bf16(O[2 * np + 1], ph, vh + 2);
                mma_bf16(O[2 * np + 1], pl, vh + 2);
                mma_bf16(O[2 * np + 1], ph, vl + 2);
            }
        }
    }

    float l0 = lsum[0];
    l0 += __shfl_xor_sync(0xffffffffu, l0, 1);
    l0 += __shfl_xor_sync(0xffffffffu, l0, 2);
    float l1 = lsum[1];
    l1 += __shfl_xor_sync(0xffffffffu, l1, 1);
    l1 += __shfl_xor_sync(0xffffffffu, l1, 2);
    const float inv0 = 1.f / l0, inv1 = 1.f / l1;

    const int b = bh >> 3;
    const int h = bh & 7;
    const int t0 = qt * 64 + wid * 16 + g;
    const size_t r0 = (size_t)b * TT + t0;
    const size_t r1 = r0 + 8;
#pragma unroll
    for (int nf = 0; nf < 8; nf++) {
        int col = h * HD + nf * 8 + 2 * q;
        uint32_t hh, ll;
        split_pair(O[nf][0] * inv0, O[nf][1] * inv0, hh, ll);
        *(uint32_t*)(g_ah + r0 * KDIM + col) = hh;
        *(uint32_t*)(g_al + r0 * KDIM + col) = ll;
        split_pair(O[nf][2] * inv1, O[nf][3] * inv1, hh, ll);
        *(uint32_t*)(g_ah + r1 * KDIM + col) = hh;
        *(uint32_t*)(g_al + r1 * KDIM + col) = ll;
    }
}

// ---------------------------------------------------------------------------
extern "C" void kernel_launch(void* const* d_in, const int* in_sizes, int n_in,
                              void* d_out, int out_size)
{
    const float* x    = (const float*)d_in[0];
    const float* cosT = (const float*)d_in[1];
    const float* sinT = (const float*)d_in[2];
    const float* Wqkv = (const float*)d_in[3];
    const float* Wout = (const float*)d_in[4];
    float* out = (float*)d_out;

    cudaFuncSetAttribute(mma_gemm_kernel<0>,
                         cudaFuncAttributeMaxDynamicSharedMemorySize, SMEM_BYTES);
    cudaFuncSetAttribute(mma_gemm_kernel<1>,
                         cudaFuncAttributeMaxDynamicSharedMemorySize, SMEM_BYTES);
    cudaFuncSetAttribute(attn_mma_kernel,
                         cudaFuncAttributeMaxDynamicSharedMemorySize, ATT_SMEM);

    uint16_t *xh, *xl, *w1h, *w1l, *w2h, *w2l, *ah, *al;
    cudaGetSymbolAddress((void**)&xh,  g_xh);
    cudaGetSymbolAddress((void**)&xl,  g_xl);
    cudaGetSymbolAddress((void**)&w1h, g_w1h);
    cudaGetSymbolAddress((void**)&w1l, g_w1l);
    cudaGetSymbolAddress((void**)&w2h, g_w2h);
    cudaGetSymbolAddress((void**)&w2l, g_w2l);
    cudaGetSymbolAddress((void**)&ah,  g_ah);
    cudaGetSymbolAddress((void**)&al,  g_al);

    {
        int n4 = (BB * TT * DD) / 4;
        split_kernel<<<n4 / 256, 256>>>((const float4*)x, (uint2*)xh, (uint2*)xl, n4);
        int w1 = (3 * DD * KDIM) / 4;
        split_kernel<<<(w1 + 255) / 256, 256>>>((const float4*)Wqkv, (uint2*)w1h, (uint2*)w1l, w1);
        int w2 = (DD * KDIM) / 4;
        split_kernel<<<(w2 + 255) / 256, 256>>>((const float4*)Wout, (uint2*)w2h, (uint2*)w2l, w2);
    }

    dim3 g1(12, 512);   // N=1536, M=65536
    mma_gemm_kernel<0><<<g1, 256, SMEM_BYTES>>>(xh, xl, w1h, w1l, cosT, sinT, nullptr);

    dim3 ga(4, BB * HH);
    attn_mma_kernel<<<ga, 128, ATT_SMEM>>>();

    dim3 g2(4, 512);    // N=512
    mma_gemm_kernel<1><<<g2, 256, SMEM_BYTES>>>(ah, al, w2h, w2l, cosT, sinT, out);
}

// round 16
// speedup vs baseline: 2.0826x; 1.2529x over previous
#include <cuda_runtime.h>
#include <cuda_fp16.h>
#include <cstdint>

// Problem constants
#define BB 256
#define TT 256
#define DD 512
#define HH 8
#define HD 64
#define KDIM 512

// Scratch (device globals; no allocation allowed)
// x: fp16 hi/lo planes ; weights: single fp16 plane
__device__ uint16_t g_xh[(size_t)BB * TT * KDIM];
__device__ uint16_t g_xl[(size_t)BB * TT * KDIM];
__device__ uint16_t g_w1h[3 * DD * KDIM];
__device__ uint16_t g_w2h[DD * KDIM];
// q/k/v: bf16 hi/lo planes (attention stays 3xbf16)
__device__ uint16_t g_qh[(size_t)BB * HH * TT * HD];
__device__ uint16_t g_ql[(size_t)BB * HH * TT * HD];
__device__ uint16_t g_kh[(size_t)BB * HH * TT * HD];
__device__ uint16_t g_kl[(size_t)BB * HH * TT * HD];
__device__ uint16_t g_vh[(size_t)BB * HH * TT * HD];
__device__ uint16_t g_vl[(size_t)BB * HH * TT * HD];
// attention out: fp16 hi/lo planes (A side of out-proj)
__device__ uint16_t g_ah[(size_t)BB * TT * KDIM];
__device__ uint16_t g_al[(size_t)BB * TT * KDIM];

// ---------------------------------------------------------------------------
// helpers
// ---------------------------------------------------------------------------
__device__ __forceinline__ uint32_t smem_u32(const void* p) {
    uint32_t a;
    asm("{ .reg .u64 t; cvta.to.shared.u64 t, %1; cvt.u32.u64 %0, t; }"
        : "=r"(a) : "l"(p));
    return a;
}

__device__ __forceinline__ void cp_async16(uint32_t dst, const void* src) {
    asm volatile("cp.async.cg.shared.global [%0], [%1], 16;"
                 :: "r"(dst), "l"(src) : "memory");
}
#define CP_COMMIT() asm volatile("cp.async.commit_group;" ::: "memory")
#define CP_WAIT1()  asm volatile("cp.async.wait_group 1;" ::: "memory")
#define CP_WAIT0()  asm volatile("cp.async.wait_group 0;" ::: "memory")

__device__ __forceinline__ void mma_bf16(float* c, const uint32_t* a, const uint32_t* b) {
    asm volatile(
        "mma.sync.aligned.m16n8k16.row.col.f32.bf16.bf16.f32 "
        "{%0,%1,%2,%3}, {%4,%5,%6,%7}, {%8,%9}, {%0,%1,%2,%3};"
        : "+f"(c[0]), "+f"(c[1]), "+f"(c[2]), "+f"(c[3])
        : "r"(a[0]), "r"(a[1]), "r"(a[2]), "r"(a[3]), "r"(b[0]), "r"(b[1]));
}

__device__ __forceinline__ void mma_f16(float* c, const uint32_t* a, const uint32_t* b) {
    asm volatile(
        "mma.sync.aligned.m16n8k16.row.col.f32.f16.f16.f32 "
        "{%0,%1,%2,%3}, {%4,%5,%6,%7}, {%8,%9}, {%0,%1,%2,%3};"
        : "+f"(c[0]), "+f"(c[1]), "+f"(c[2]), "+f"(c[3])
        : "r"(a[0]), "r"(a[1]), "r"(a[2]), "r"(a[3]), "r"(b[0]), "r"(b[1]));
}

#define LDM4(r0, r1, r2, r3, addr) \
    asm volatile("ldmatrix.sync.aligned.m8n8.x4.shared.b16 {%0,%1,%2,%3}, [%4];" \
                 : "=r"(r0), "=r"(r1), "=r"(r2), "=r"(r3) : "r"(addr))
#define LDM4T(r0, r1, r2, r3, addr) \
    asm volatile("ldmatrix.sync.aligned.m8n8.x4.trans.shared.b16 {%0,%1,%2,%3}, [%4];" \
                 : "=r"(r0), "=r"(r1), "=r"(r2), "=r"(r3) : "r"(addr))

__device__ __forceinline__ float ex2f(float x) {
    float y;
    asm("ex2.approx.ftz.f32 %0, %1;" : "=f"(y) : "f"(x));
    return y;
}

// bf16 split (attention path)
__device__ __forceinline__ void split_pair(float x0, float x1,
                                           uint32_t& hi, uint32_t& lo) {
    asm("cvt.rn.bf16x2.f32 %0, %1, %2;" : "=r"(hi) : "f"(x1), "f"(x0));
    float h0 = __uint_as_float(hi << 16);
    float h1 = __uint_as_float(hi & 0xffff0000u);
    asm("cvt.rn.bf16x2.f32 %0, %1, %2;" : "=r"(lo) : "f"(x1 - h1), "f"(x0 - h0));
}

// fp16 split (GEMM A-side)
__device__ __forceinline__ void split_pair_f16(float x0, float x1,
                                               uint32_t& hi, uint32_t& lo) {
    __half2 h = __floats2half2_rn(x0, x1);
    hi = *(uint32_t*)&h;
    float r0 = x0 - __low2float(h);
    float r1 = x1 - __high2float(h);
    __half2 l = __floats2half2_rn(r0, r1);
    lo = *(uint32_t*)&l;
}

// ---------------------------------------------------------------------------
// Splitters
// ---------------------------------------------------------------------------
__global__ void __launch_bounds__(256) split16_kernel(
    const float4* __restrict__ in,
    uint2* __restrict__ oh, uint2* __restrict__ ol, int n4)
{
    int i = blockIdx.x * 256 + threadIdx.x;
    if (i < n4) {
        float4 v = in[i];
        uint2 h, l;
        split_pair_f16(v.x, v.y, h.x, l.x);
        split_pair_f16(v.z, v.w, h.y, l.y);
        oh[i] = h;
        ol[i] = l;
    }
}

__global__ void __launch_bounds__(256) cvt16_kernel(
    const float4* __restrict__ in, uint2* __restrict__ oh, int n4)
{
    int i = blockIdx.x * 256 + threadIdx.x;
    if (i < n4) {
        float4 v = in[i];
        __half2 a = __floats2half2_rn(v.x, v.y);
        __half2 b = __floats2half2_rn(v.z, v.w);
        oh[i] = make_uint2(*(uint32_t*)&a, *(uint32_t*)&b);
    }
}

// ---------------------------------------------------------------------------
// 2xFP16 GEMM: C = (Ah + Al) @ Bh^T ; A fp16 hi/lo planes, B single fp16.
// MODE 0: RoPE + write bf16-split q/k/v planes. MODE 1: fp32 dst_out.
// 256 thr = 8 warps (2m x 4n); warp 64x32; CTA 128x128; BK=32;
// 3 stages (3 planes x 10240B = 30720B/stage), ONE barrier per K-step.
// ---------------------------------------------------------------------------
#define STRIDE_B 80
#define PLANE_B (128 * STRIDE_B)       // 10240
#define STG_B   (3 * PLANE_B)          // 30720
#define SMEM_BYTES (3 * STG_B)         // 92160

template <int MODE>
__global__ void __launch_bounds__(256, 2) mma_gemm_kernel(
    const uint16_t* __restrict__ Ah, const uint16_t* __restrict__ Al,
    const uint16_t* __restrict__ Bh,
    const float* __restrict__ cosT,
    const float* __restrict__ sinT,
    float* __restrict__ dst_out)
{
    extern __shared__ char smc[];
    const uint32_t sb = smem_u32(smc);

    const int tid  = threadIdx.x;
    const int wid  = tid >> 5;      // 0..7
    const int lane = tid & 31;
    const int g    = lane >> 2;
    const int q    = lane & 3;
    const int bm   = blockIdx.y * 128;
    const int bn   = blockIdx.x * 128;
    const int wm   = wid & 1;       // 2 m-warps
    const int wn   = wid >> 1;      // 4 n-warps

    float c[4][4][4];
#pragma unroll
    for (int mf = 0; mf < 4; mf++)
#pragma unroll
        for (int nf = 0; nf < 4; nf++)
#pragma unroll
            for (int r = 0; r < 4; r++) c[mf][nf][r] = 0.f;

    const uint32_t a_off =
        (uint32_t)(wm * 64 + (lane & 15)) * STRIDE_B + (lane >> 4) * 16;
    const uint32_t b_off =
        (uint32_t)(wn * 32 + (lane & 7) + ((lane >> 4) << 3)) * STRIDE_B +
        ((lane >> 3) & 1) * 16;

    // 1536 16B chunks per stage / 256 threads = 6 each
    auto load_stage = [&](int s, int kt) {
        const uint32_t base = sb + (uint32_t)s * STG_B;
#pragma unroll
        for (int i = 0; i < 6; i++) {
            int e   = tid + i * 256;
            int cch = e & 3;
            int row = (e >> 2) & 127;
            int pm  = e >> 9;           // 0=Ah 1=Al 2=Bh
            const uint16_t* src;
            if (pm == 0)      src = Ah + (size_t)(bm + row) * KDIM;
            else if (pm == 1) src = Al + (size_t)(bm + row) * KDIM;
            else              src = Bh + (size_t)(bn + row) * KDIM;
            cp_async16(base + pm * PLANE_B + row * STRIDE_B + cch * 16,
                       src + kt * 32 + cch * 8);
        }
    };

    load_stage(0, 0); CP_COMMIT();
    load_stage(1, 1); CP_COMMIT();

#pragma unroll 1
    for (int kt = 0; kt < 16; kt++) {
        CP_WAIT1();
        __syncthreads();               // data ready + prev reads done
        if (kt + 2 < 16) load_stage((kt + 2) % 3, kt + 2);
        CP_COMMIT();

        const uint32_t st = sb + (uint32_t)(kt % 3) * STG_B;
        const uint32_t aH = st + a_off;
        const uint32_t aL = aH + PLANE_B;
        const uint32_t bH = st + 2 * PLANE_B + b_off;

#pragma unroll
        for (int s2 = 0; s2 < 2; s2++) {
            const uint32_t ko = s2 * 32;
            uint32_t bh[4][2];
            LDM4(bh[0][0], bh[0][1], bh[1][0], bh[1][1], bH + ko);
            LDM4(bh[2][0], bh[2][1], bh[3][0], bh[3][1], bH + 16 * STRIDE_B + ko);
#pragma unroll
            for (int mf = 0; mf < 4; mf++) {
                uint32_t ah[4], al[4];
                LDM4(ah[0], ah[1], ah[2], ah[3], aH + mf * 16 * STRIDE_B + ko);
                LDM4(al[0], al[1], al[2], al[3], aL + mf * 16 * STRIDE_B + ko);
#pragma unroll
                for (int nf = 0; nf < 4; nf++) {
                    mma_f16(c[mf][nf], ah, bh[nf]);
                    mma_f16(c[mf][nf], al, bh[nf]);
                }
            }
        }
    }

    // -------- epilogue --------
#pragma unroll
    for (int mf = 0; mf < 4; mf++) {
#pragma unroll
        for (int rr = 0; rr < 2; rr++) {
            int m = bm + wm * 64 + mf * 16 + g + rr * 8;
#pragma unroll
            for (int nf = 0; nf < 4; nf++) {
                int n = bn + wn * 32 + nf * 8 + 2 * q;
                float v0 = c[mf][nf][rr * 2 + 0];
                float v1 = c[mf][nf][rr * 2 + 1];
                if (MODE == 0) {
                    int bI = m >> 8, t = m & 255;
                    int sec = n >> 9, h = (n >> 6) & 7, d = n & 63;
                    if (sec < 2) {
                        float co = __ldg(cosT + t * HD + d);
                        float sn = __ldg(sinT + t * HD + d);
                        float t0 = v0 * co - v1 * sn;
                        float t1 = v1 * co + v0 * sn;
                        v0 = t0; v1 = t1;
                    }
                    uint16_t* dh = (sec == 0) ? g_qh : ((sec == 1) ? g_kh : g_vh);
                    uint16_t* dl = (sec == 0) ? g_ql : ((sec == 1) ? g_kl : g_vl);
                    size_t idx = (((size_t)bI * HH + h) * TT + t) * HD + d;
                    uint32_t hh, ll;
                    split_pair(v0, v1, hh, ll);
                    *(uint32_t*)(dh + idx) = hh;
                    *(uint32_t*)(dl + idx) = ll;
                } else {
                    *(float2*)(dst_out + (size_t)m * DD + n) = make_float2(v0, v1);
                }
            }
        }
    }
}

// ---------------------------------------------------------------------------
// Tensor-core causal flash attention (3xbf16) — proven; epilogue now writes
// fp16 hi/lo planes for the 2xFP16 out-proj.
// ---------------------------------------------------------------------------
#define ASTRIDE 144
#define APLANE (64 * ASTRIDE)          // 9216
#define KV_STG (4 * APLANE)            // 36864
#define ATT_SMEM (2 * APLANE + 2 * KV_STG)  // 92160

__global__ void __launch_bounds__(128, 2) attn_mma_kernel()
{
    extern __shared__ char smc[];
    const uint32_t sb = smem_u32(smc);

    const int qt  = blockIdx.x;        // 0..3
    const int bh  = blockIdx.y;        // 0..2047
    const int tid = threadIdx.x;
    const int wid = tid >> 5;
    const int lane = tid & 31;
    const int g = lane >> 2;
    const int q = lane & 3;

    const size_t bhoff = (size_t)bh * TT * HD;
    const uint16_t* Qh = g_qh + bhoff + (size_t)qt * 64 * HD;
    const uint16_t* Ql = g_ql + bhoff + (size_t)qt * 64 * HD;
    const uint16_t* Kh = g_kh + bhoff;
    const uint16_t* Kl = g_kl + bhoff;
    const uint16_t* Vh = g_vh + bhoff;
    const uint16_t* Vl = g_vl + bhoff;

#pragma unroll
    for (int i = 0; i < 8; i++) {
        int e = tid + i * 128;
        int pl = e >> 9;
        int row = (e >> 3) & 63;
        int ch = e & 7;
        const uint16_t* src = (pl ? Ql : Qh) + (size_t)row * HD + ch * 8;
        cp_async16(sb + pl * APLANE + row * ASTRIDE + ch * 16, src);
    }
    CP_COMMIT();

    auto load_kv = [&](int s, int kt) {
        const uint32_t base = sb + 2 * APLANE + (uint32_t)s * KV_STG;
#pragma unroll
        for (int i = 0; i < 16; i++) {
            int e = tid + i * 128;
            int pm = e >> 9;           // 0=Kh 1=Kl 2=Vh 3=Vl
            int row = (e >> 3) & 63;
            int ch = e & 7;
            const uint16_t* src =
                (pm == 0 ? Kh : pm == 1 ? Kl : pm == 2 ? Vh : Vl) +
                (size_t)(kt * 64 + row) * HD + ch * 8;
            cp_async16(base + pm * APLANE + row * ASTRIDE + ch * 16, src);
        }
    };
    load_kv(0, 0); CP_COMMIT();

    CP_WAIT1();
    __syncthreads();

    uint32_t qfh[4][4], qfl[4][4];
    {
        const uint32_t qa = sb + (uint32_t)(wid * 16 + (lane & 15)) * ASTRIDE +
                            (lane >> 4) * 16;
#pragma unroll
        for (int kc = 0; kc < 4; kc++) {
            LDM4(qfh[kc][0], qfh[kc][1], qfh[kc][2], qfh[kc][3], qa + kc * 32);
            LDM4(qfl[kc][0], qfl[kc][1], qfl[kc][2], qfl[kc][3],
                 qa + APLANE + kc * 32);
        }
    }

    float O[8][4];
#pragma unroll
    for (int nf = 0; nf < 8; nf++)
#pragma unroll
        for (int j = 0; j < 4; j++) O[nf][j] = 0.f;
    float m2[2] = {-1e30f, -1e30f};
    float lsum[2] = {0.f, 0.f};
    const float sc2 = 0.125f * 1.44269504088896f;   // scale * log2(e)
    const int row0 = qt * 64 + wid * 16 + g;

    const uint32_t kaddr_off =
        (uint32_t)((lane & 7) + ((lane >> 4) << 3)) * ASTRIDE +
        ((lane >> 3) & 1) * 16;
    const uint32_t vaddr_off =
        (uint32_t)(lane & 15) * ASTRIDE + (lane >> 4) * 16;

#pragma unroll 1
    for (int kt = 0; kt <= qt; kt++) {
        __syncthreads();
        if (kt < qt) {
            load_kv((kt + 1) & 1, kt + 1);
            CP_COMMIT();
            CP_WAIT1();
        } else {
            CP_WAIT0();
        }
        __syncthreads();

        const uint32_t kb = sb + 2 * APLANE + (uint32_t)(kt & 1) * KV_STG;

        float s[8][4];
#pragma unroll
        for (int nf = 0; nf < 8; nf++)
#pragma unroll
            for (int j = 0; j < 4; j++) s[nf][j] = 0.f;

#pragma unroll
        for (int kc = 0; kc < 4; kc++) {
#pragma unroll
            for (int np = 0; np < 4; np++) {
                uint32_t kh[4], kl[4];
                const uint32_t ka = kb + kaddr_off + np * 16 * ASTRIDE + kc * 32;
                LDM4(kh[0], kh[1], kh[2], kh[3], ka);
                LDM4(kl[0], kl[1], kl[2], kl[3], ka + APLANE);
                mma_bf16(s[2 * np],     qfh[kc], kh);
                mma_bf16(s[2 * np],     qfl[kc], kh);
                mma_bf16(s[2 * np],     qfh[kc], kl);
                mma_bf16(s[2 * np + 1], qfh[kc], kh + 2);
                mma_bf16(s[2 * np + 1], qfl[kc], kh + 2);
                mma_bf16(s[2 * np + 1], qfh[kc], kl + 2);
            }
        }

        float mx0 = -1e30f, mx1 = -1e30f;
#pragma unroll
        for (int nf = 0; nf < 8; nf++) {
            int colb = kt * 64 + nf * 8 + 2 * q;
#pragma unroll
            for (int j = 0; j < 4; j++) {
                float v = s[nf][j] * sc2;
                if (kt == qt) {
                    int col = colb + (j & 1);
                    int row = row0 + ((j >> 1) << 3);
                    if (col > row) v = -1e30f;
                }
                s[nf][j] = v;
            }
            mx0 = fmaxf(mx0, fmaxf(s[nf][0], s[nf][1]));
            mx1 = fmaxf(mx1, fmaxf(s[nf][2], s[nf][3]));
        }
        mx0 = fmaxf(mx0, __shfl_xor_sync(0xffffffffu, mx0, 1));
        mx0 = fmaxf(mx0, __shfl_xor_sync(0xffffffffu, mx0, 2));
        mx1 = fmaxf(mx1, __shfl_xor_sync(0xffffffffu, mx1, 1));
        mx1 = fmaxf(mx1, __shfl_xor_sync(0xffffffffu, mx1, 2));
        float mn0 = fmaxf(m2[0], mx0), mn1 = fmaxf(m2[1], mx1);
        float a0 = ex2f(m2[0] - mn0), a1 = ex2f(m2[1] - mn1);
        m2[0] = mn0; m2[1] = mn1;
        float ls0 = 0.f, ls1 = 0.f;
#pragma unroll
        for (int nf = 0; nf < 8; nf++) {
            float p0 = ex2f(s[nf][0] - mn0);
            float p1 = ex2f(s[nf][1] - mn0);
            float p2 = ex2f(s[nf][2] - mn1);
            float p3 = ex2f(s[nf][3] - mn1);
            s[nf][0] = p0; s[nf][1] = p1; s[nf][2] = p2; s[nf][3] = p3;
            ls0 += p0 + p1; ls1 += p2 + p3;
            O[nf][0] *= a0; O[nf][1] *= a0;
            O[nf][2] *= a1; O[nf][3] *= a1;
        }
        lsum[0] = lsum[0] * a0 + ls0;
        lsum[1] = lsum[1] * a1 + ls1;

#pragma unroll
        for (int kc = 0; kc < 4; kc++) {
            uint32_t ph[4], pl[4];
            split_pair(s[2 * kc][0],     s[2 * kc][1],     ph[0], pl[0]);
            split_pair(s[2 * kc][2],     s[2 * kc][3],     ph[1], pl[1]);
            split_pair(s[2 * kc + 1][0], s[2 * kc + 1][1], ph[2], pl[2]);
            split_pair(s[2 * kc + 1][2], s[2 * kc + 1][3], ph[3], pl[3]);
#pragma unroll
            for (int np = 0; np < 4; np++) {
                uint32_t vh[4], vl[4];
                const uint32_t va = kb + 2 * APLANE + vaddr_off +
                                    kc * 16 * ASTRIDE + np * 32;
                LDM4T(vh[0], vh[1], vh[2], vh[3], va);
                LDM4T(vl[0], vl[1], vl[2], vl[3], va + APLANE);
                mma_bf16(O[2 * np],     ph, vh);
                mma_bf16(O[2 * np],     pl, vh);
                mma_bf16(O[2 * np],     ph, vl);
                mma_bf16(O[2 * np + 1], ph, vh + 2);
                mma_bf16(O[2 * np + 1], pl, vh + 2);
                mma_bf16(O[2 * np + 1], ph, vl + 2);
            }
        }
    }

    float l0 = lsum[0];
    l0 += __shfl_xor_sync(0xffffffffu, l0, 1);
    l0 += __shfl_xor_sync(0xffffffffu, l0, 2);
    float l1 = lsum[1];
    l1 += __shfl_xor_sync(0xffffffffu, l1, 1);
    l1 += __shfl_xor_sync(0xffffffffu, l1, 2);
    const float inv0 = 1.f / l0, inv1 = 1.f / l1;

    const int b = bh >> 3;
    const int h = bh & 7;
    const int t0 = qt * 64 + wid * 16 + g;
    const size_t r0 = (size_t)b * TT + t0;
    const size_t r1 = r0 + 8;
#pragma unroll
    for (int nf = 0; nf < 8; nf++) {
        int col = h * HD + nf * 8 + 2 * q;
        uint32_t hh, ll;
        split_pair_f16(O[nf][0] * inv0, O[nf][1] * inv0, hh, ll);
        *(uint32_t*)(g_ah + r0 * KDIM + col) = hh;
        *(uint32_t*)(g_al + r0 * KDIM + col) = ll;
        split_pair_f16(O[nf][2] * inv1, O[nf][3] * inv1, hh, ll);
        *(uint32_t*)(g_ah + r1 * KDIM + col) = hh;
        *(uint32_t*)(g_al + r1 * KDIM + col) = ll;
    }
}

// ---------------------------------------------------------------------------
extern "C" void kernel_launch(void* const* d_in, const int* in_sizes, int n_in,
                              void* d_out, int out_size)
{
    const float* x    = (const float*)d_in[0];
    const float* cosT = (const float*)d_in[1];
    const float* sinT = (const float*)d_in[2];
    const float* Wqkv = (const float*)d_in[3];
    const float* Wout = (const float*)d_in[4];
    float* out = (float*)d_out;

    cudaFuncSetAttribute(mma_gemm_kernel<0>,
                         cudaFuncAttributeMaxDynamicSharedMemorySize, SMEM_BYTES);
    cudaFuncSetAttribute(mma_gemm_kernel<1>,
                         cudaFuncAttributeMaxDynamicSharedMemorySize, SMEM_BYTES);
    cudaFuncSetAttribute(attn_mma_kernel,
                         cudaFuncAttributeMaxDynamicSharedMemorySize, ATT_SMEM);

    uint16_t *xh, *xl, *w1h, *w2h, *ah, *al;
    cudaGetSymbolAddress((void**)&xh,  g_xh);
    cudaGetSymbolAddress((void**)&xl,  g_xl);
    cudaGetSymbolAddress((void**)&w1h, g_w1h);
    cudaGetSymbolAddress((void**)&w2h, g_w2h);
    cudaGetSymbolAddress((void**)&ah,  g_ah);
    cudaGetSymbolAddress((void**)&al,  g_al);

    {
        int n4 = (BB * TT * DD) / 4;
        split16_kernel<<<n4 / 256, 256>>>((const float4*)x, (uint2*)xh, (uint2*)xl, n4);
        int w1 = (3 * DD * KDIM) / 4;
        cvt16_kernel<<<(w1 + 255) / 256, 256>>>((const float4*)Wqkv, (uint2*)w1h, w1);
        int w2 = (DD * KDIM) / 4;
        cvt16_kernel<<<(w2 + 255) / 256, 256>>>((const float4*)Wout, (uint2*)w2h, w2);
    }

    dim3 g1(12, 512);   // N=1536, M=65536
    mma_gemm_kernel<0><<<g1, 256, SMEM_BYTES>>>(xh, xl, w1h, cosT, sinT, nullptr);

    dim3 ga(4, BB * HH);
    attn_mma_kernel<<<ga, 128, ATT_SMEM>>>();

    dim3 g2(4, 512);    // N=512
    mma_gemm_kernel<1><<<g2, 256, SMEM_BYTES>>>(ah, al, w2h, cosT, sinT, out);
}

// round 17
// speedup vs baseline: 2.9377x; 1.4106x over previous
#include <cuda_runtime.h>
#include <cuda_fp16.h>
#include <cstdint>

// Problem constants
#define BB 256
#define TT 256
#define DD 512
#define HH 8
#define HD 64
#define KDIM 512

// Scratch (device globals; no allocation allowed)
// GEMM operands: single fp16 planes
__device__ uint16_t g_xh[(size_t)BB * TT * KDIM];
__device__ uint16_t g_w1h[3 * DD * KDIM];
__device__ uint16_t g_w2h[DD * KDIM];
// q/k/v: bf16 hi/lo planes (attention stays 3xbf16 — precision anchor)
__device__ uint16_t g_qh[(size_t)BB * HH * TT * HD];
__device__ uint16_t g_ql[(size_t)BB * HH * TT * HD];
__device__ uint16_t g_kh[(size_t)BB * HH * TT * HD];
__device__ uint16_t g_kl[(size_t)BB * HH * TT * HD];
__device__ uint16_t g_vh[(size_t)BB * HH * TT * HD];
__device__ uint16_t g_vl[(size_t)BB * HH * TT * HD];
// attention out: single fp16 plane (A side of out-proj)
__device__ uint16_t g_ah[(size_t)BB * TT * KDIM];

// ---------------------------------------------------------------------------
// helpers
// ---------------------------------------------------------------------------
__device__ __forceinline__ uint32_t smem_u32(const void* p) {
    uint32_t a;
    asm("{ .reg .u64 t; cvta.to.shared.u64 t, %1; cvt.u32.u64 %0, t; }"
        : "=r"(a) : "l"(p));
    return a;
}

__device__ __forceinline__ void cp_async16(uint32_t dst, const void* src) {
    asm volatile("cp.async.cg.shared.global [%0], [%1], 16;"
                 :: "r"(dst), "l"(src) : "memory");
}
#define CP_COMMIT() asm volatile("cp.async.commit_group;" ::: "memory")
#define CP_WAIT1()  asm volatile("cp.async.wait_group 1;" ::: "memory")
#define CP_WAIT0()  asm volatile("cp.async.wait_group 0;" ::: "memory")

__device__ __forceinline__ void mma_bf16(float* c, const uint32_t* a, const uint32_t* b) {
    asm volatile(
        "mma.sync.aligned.m16n8k16.row.col.f32.bf16.bf16.f32 "
        "{%0,%1,%2,%3}, {%4,%5,%6,%7}, {%8,%9}, {%0,%1,%2,%3};"
        : "+f"(c[0]), "+f"(c[1]), "+f"(c[2]), "+f"(c[3])
        : "r"(a[0]), "r"(a[1]), "r"(a[2]), "r"(a[3]), "r"(b[0]), "r"(b[1]));
}

__device__ __forceinline__ void mma_f16(float* c, const uint32_t* a, const uint32_t* b) {
    asm volatile(
        "mma.sync.aligned.m16n8k16.row.col.f32.f16.f16.f32 "
        "{%0,%1,%2,%3}, {%4,%5,%6,%7}, {%8,%9}, {%0,%1,%2,%3};"
        : "+f"(c[0]), "+f"(c[1]), "+f"(c[2]), "+f"(c[3])
        : "r"(a[0]), "r"(a[1]), "r"(a[2]), "r"(a[3]), "r"(b[0]), "r"(b[1]));
}

#define LDM4(r0, r1, r2, r3, addr) \
    asm volatile("ldmatrix.sync.aligned.m8n8.x4.shared.b16 {%0,%1,%2,%3}, [%4];" \
                 : "=r"(r0), "=r"(r1), "=r"(r2), "=r"(r3) : "r"(addr))
#define LDM4T(r0, r1, r2, r3, addr) \
    asm volatile("ldmatrix.sync.aligned.m8n8.x4.trans.shared.b16 {%0,%1,%2,%3}, [%4];" \
                 : "=r"(r0), "=r"(r1), "=r"(r2), "=r"(r3) : "r"(addr))

__device__ __forceinline__ float ex2f(float x) {
    float y;
    asm("ex2.approx.ftz.f32 %0, %1;" : "=f"(y) : "f"(x));
    return y;
}

// bf16 split (attention path)
__device__ __forceinline__ void split_pair(float x0, float x1,
                                           uint32_t& hi, uint32_t& lo) {
    asm("cvt.rn.bf16x2.f32 %0, %1, %2;" : "=r"(hi) : "f"(x1), "f"(x0));
    float h0 = __uint_as_float(hi << 16);
    float h1 = __uint_as_float(hi & 0xffff0000u);
    asm("cvt.rn.bf16x2.f32 %0, %1, %2;" : "=r"(lo) : "f"(x1 - h1), "f"(x0 - h0));
}

// ---------------------------------------------------------------------------
// fp32 -> single fp16 plane converter
// ---------------------------------------------------------------------------
__global__ void __launch_bounds__(256) cvt16_kernel(
    const float4* __restrict__ in, uint2* __restrict__ oh, int n4)
{
    int i = blockIdx.x * 256 + threadIdx.x;
    if (i < n4) {
        float4 v = in[i];
        __half2 a = __floats2half2_rn(v.x, v.y);
        __half2 b = __floats2half2_rn(v.z, v.w);
        oh[i] = make_uint2(*(uint32_t*)&a, *(uint32_t*)&b);
    }
}

// ---------------------------------------------------------------------------
// Single-pass FP16 GEMM: C = Ah @ Bh^T ; both single fp16 planes.
// MODE 0: RoPE + write bf16-split q/k/v planes. MODE 1: fp32 dst_out.
// 256 thr = 8 warps (2m x 4n); warp 64x32; CTA 128x128; BK=32;
// 3 stages (2 planes x 10240B = 20480B/stage), ONE barrier per K-step.
// ---------------------------------------------------------------------------
#define STRIDE_B 80
#define PLANE_B (128 * STRIDE_B)       // 10240
#define STG_B   (2 * PLANE_B)          // 20480
#define SMEM_BYTES (3 * STG_B)         // 61440

template <int MODE>
__global__ void __launch_bounds__(256, 2) mma_gemm_kernel(
    const uint16_t* __restrict__ Ah,
    const uint16_t* __restrict__ Bh,
    const float* __restrict__ cosT,
    const float* __restrict__ sinT,
    float* __restrict__ dst_out)
{
    extern __shared__ char smc[];
    const uint32_t sb = smem_u32(smc);

    const int tid  = threadIdx.x;
    const int wid  = tid >> 5;      // 0..7
    const int lane = tid & 31;
    const int g    = lane >> 2;
    const int q    = lane & 3;
    const int bm   = blockIdx.y * 128;
    const int bn   = blockIdx.x * 128;
    const int wm   = wid & 1;       // 2 m-warps
    const int wn   = wid >> 1;      // 4 n-warps

    float c[4][4][4];
#pragma unroll
    for (int mf = 0; mf < 4; mf++)
#pragma unroll
        for (int nf = 0; nf < 4; nf++)
#pragma unroll
            for (int r = 0; r < 4; r++) c[mf][nf][r] = 0.f;

    const uint32_t a_off =
        (uint32_t)(wm * 64 + (lane & 15)) * STRIDE_B + (lane >> 4) * 16;
    const uint32_t b_off =
        (uint32_t)(wn * 32 + (lane & 7) + ((lane >> 4) << 3)) * STRIDE_B +
        ((lane >> 3) & 1) * 16;

    // 1024 16B chunks per stage / 256 threads = 4 each
    auto load_stage = [&](int s, int kt) {
        const uint32_t base = sb + (uint32_t)s * STG_B;
#pragma unroll
        for (int i = 0; i < 4; i++) {
            int e   = tid + i * 256;
            int cch = e & 3;
            int row = (e >> 2) & 127;
            int pm  = e >> 9;           // 0=A 1=B
            const uint16_t* src = (pm == 0)
                ? Ah + (size_t)(bm + row) * KDIM
                : Bh + (size_t)(bn + row) * KDIM;
            cp_async16(base + pm * PLANE_B + row * STRIDE_B + cch * 16,
                       src + kt * 32 + cch * 8);
        }
    };

    load_stage(0, 0); CP_COMMIT();
    load_stage(1, 1); CP_COMMIT();

#pragma unroll 1
    for (int kt = 0; kt < 16; kt++) {
        CP_WAIT1();
        __syncthreads();               // data ready + prev reads done
        if (kt + 2 < 16) load_stage((kt + 2) % 3, kt + 2);
        CP_COMMIT();

        const uint32_t st = sb + (uint32_t)(kt % 3) * STG_B;
        const uint32_t aH = st + a_off;
        const uint32_t bH = st + PLANE_B + b_off;

#pragma unroll
        for (int s2 = 0; s2 < 2; s2++) {
            const uint32_t ko = s2 * 32;
            uint32_t bh[4][2];
            LDM4(bh[0][0], bh[0][1], bh[1][0], bh[1][1], bH + ko);
            LDM4(bh[2][0], bh[2][1], bh[3][0], bh[3][1], bH + 16 * STRIDE_B + ko);
#pragma unroll
            for (int mf = 0; mf < 4; mf++) {
                uint32_t ah[4];
                LDM4(ah[0], ah[1], ah[2], ah[3], aH + mf * 16 * STRIDE_B + ko);
#pragma unroll
                for (int nf = 0; nf < 4; nf++)
                    mma_f16(c[mf][nf], ah, bh[nf]);
            }
        }
    }

    // -------- epilogue --------
#pragma unroll
    for (int mf = 0; mf < 4; mf++) {
#pragma unroll
        for (int rr = 0; rr < 2; rr++) {
            int m = bm + wm * 64 + mf * 16 + g + rr * 8;
#pragma unroll
            for (int nf = 0; nf < 4; nf++) {
                int n = bn + wn * 32 + nf * 8 + 2 * q;
                float v0 = c[mf][nf][rr * 2 + 0];
                float v1 = c[mf][nf][rr * 2 + 1];
                if (MODE == 0) {
                    int bI = m >> 8, t = m & 255;
                    int sec = n >> 9, h = (n >> 6) & 7, d = n & 63;
                    if (sec < 2) {
                        float co = __ldg(cosT + t * HD + d);
                        float sn = __ldg(sinT + t * HD + d);
                        float t0 = v0 * co - v1 * sn;
                        float t1 = v1 * co + v0 * sn;
                        v0 = t0; v1 = t1;
                    }
                    uint16_t* dh = (sec == 0) ? g_qh : ((sec == 1) ? g_kh : g_vh);
                    uint16_t* dl = (sec == 0) ? g_ql : ((sec == 1) ? g_kl : g_vl);
                    size_t idx = (((size_t)bI * HH + h) * TT + t) * HD + d;
                    uint32_t hh, ll;
                    split_pair(v0, v1, hh, ll);
                    *(uint32_t*)(dh + idx) = hh;
                    *(uint32_t*)(dl + idx) = ll;
                } else {
                    *(float2*)(dst_out + (size_t)m * DD + n) = make_float2(v0, v1);
                }
            }
        }
    }
}

// ---------------------------------------------------------------------------
// Tensor-core causal flash attention (3xbf16) — proven; epilogue writes
// a single fp16 plane for the 1-pass fp16 out-proj.
// ---------------------------------------------------------------------------
#define ASTRIDE 144
#define APLANE (64 * ASTRIDE)          // 9216
#define KV_STG (4 * APLANE)            // 36864
#define ATT_SMEM (2 * APLANE + 2 * KV_STG)  // 92160

__global__ void __launch_bounds__(128, 2) attn_mma_kernel()
{
    extern __shared__ char smc[];
    const uint32_t sb = smem_u32(smc);

    const int qt  = blockIdx.x;        // 0..3
    const int bh  = blockIdx.y;        // 0..2047
    const int tid = threadIdx.x;
    const int wid = tid >> 5;
    const int lane = tid & 31;
    const int g = lane >> 2;
    const int q = lane & 3;

    const size_t bhoff = (size_t)bh * TT * HD;
    const uint16_t* Qh = g_qh + bhoff + (size_t)qt * 64 * HD;
    const uint16_t* Ql = g_ql + bhoff + (size_t)qt * 64 * HD;
    const uint16_t* Kh = g_kh + bhoff;
    const uint16_t* Kl = g_kl + bhoff;
    const uint16_t* Vh = g_vh + bhoff;
    const uint16_t* Vl = g_vl + bhoff;

#pragma unroll
    for (int i = 0; i < 8; i++) {
        int e = tid + i * 128;
        int pl = e >> 9;
        int row = (e >> 3) & 63;
        int ch = e & 7;
        const uint16_t* src = (pl ? Ql : Qh) + (size_t)row * HD + ch * 8;
        cp_async16(sb + pl * APLANE + row * ASTRIDE + ch * 16, src);
    }
    CP_COMMIT();

    auto load_kv = [&](int s, int kt) {
        const uint32_t base = sb + 2 * APLANE + (uint32_t)s * KV_STG;
#pragma unroll
        for (int i = 0; i < 16; i++) {
            int e = tid + i * 128;
            int pm = e >> 9;           // 0=Kh 1=Kl 2=Vh 3=Vl
            int row = (e >> 3) & 63;
            int ch = e & 7;
            const uint16_t* src =
                (pm == 0 ? Kh : pm == 1 ? Kl : pm == 2 ? Vh : Vl) +
                (size_t)(kt * 64 + row) * HD + ch * 8;
            cp_async16(base + pm * APLANE + row * ASTRIDE + ch * 16, src);
        }
    };
    load_kv(0, 0); CP_COMMIT();

    CP_WAIT1();
    __syncthreads();

    uint32_t qfh[4][4], qfl[4][4];
    {
        const uint32_t qa = sb + (uint32_t)(wid * 16 + (lane & 15)) * ASTRIDE +
                            (lane >> 4) * 16;
#pragma unroll
        for (int kc = 0; kc < 4; kc++) {
            LDM4(qfh[kc][0], qfh[kc][1], qfh[kc][2], qfh[kc][3], qa + kc * 32);
            LDM4(qfl[kc][0], qfl[kc][1], qfl[kc][2], qfl[kc][3],
                 qa + APLANE + kc * 32);
        }
    }

    float O[8][4];
#pragma unroll
    for (int nf = 0; nf < 8; nf++)
#pragma unroll
        for (int j = 0; j < 4; j++) O[nf][j] = 0.f;
    float m2[2] = {-1e30f, -1e30f};
    float lsum[2] = {0.f, 0.f};
    const float sc2 = 0.125f * 1.44269504088896f;   // scale * log2(e)
    const int row0 = qt * 64 + wid * 16 + g;

    const uint32_t kaddr_off =
        (uint32_t)((lane & 7) + ((lane >> 4) << 3)) * ASTRIDE +
        ((lane >> 3) & 1) * 16;
    const uint32_t vaddr_off =
        (uint32_t)(lane & 15) * ASTRIDE + (lane >> 4) * 16;

#pragma unroll 1
    for (int kt = 0; kt <= qt; kt++) {
        __syncthreads();
        if (kt < qt) {
            load_kv((kt + 1) & 1, kt + 1);
            CP_COMMIT();
            CP_WAIT1();
        } else {
            CP_WAIT0();
        }
        __syncthreads();

        const uint32_t kb = sb + 2 * APLANE + (uint32_t)(kt & 1) * KV_STG;

        float s[8][4];
#pragma unroll
        for (int nf = 0; nf < 8; nf++)
#pragma unroll
            for (int j = 0; j < 4; j++) s[nf][j] = 0.f;

#pragma unroll
        for (int kc = 0; kc < 4; kc++) {
#pragma unroll
            for (int np = 0; np < 4; np++) {
                uint32_t kh[4], kl[4];
                const uint32_t ka = kb + kaddr_off + np * 16 * ASTRIDE + kc * 32;
                LDM4(kh[0], kh[1], kh[2], kh[3], ka);
                LDM4(kl[0], kl[1], kl[2], kl[3], ka + APLANE);
                mma_bf16(s[2 * np],     qfh[kc], kh);
                mma_bf16(s[2 * np],     qfl[kc], kh);
                mma_bf16(s[2 * np],     qfh[kc], kl);
                mma_bf16(s[2 * np + 1], qfh[kc], kh + 2);
                mma_bf16(s[2 * np + 1], qfl[kc], kh + 2);
                mma_bf16(s[2 * np + 1], qfh[kc], kl + 2);
            }
        }

        float mx0 = -1e30f, mx1 = -1e30f;
#pragma unroll
        for (int nf = 0; nf < 8; nf++) {
            int colb = kt * 64 + nf * 8 + 2 * q;
#pragma unroll
            for (int j = 0; j < 4; j++) {
                float v = s[nf][j] * sc2;
                if (kt == qt) {
                    int col = colb + (j & 1);
                    int row = row0 + ((j >> 1) << 3);
                    if (col > row) v = -1e30f;
                }
                s[nf][j] = v;
            }
            mx0 = fmaxf(mx0, fmaxf(s[nf][0], s[nf][1]));
            mx1 = fmaxf(mx1, fmaxf(s[nf][2], s[nf][3]));
        }
        mx0 = fmaxf(mx0, __shfl_xor_sync(0xffffffffu, mx0, 1));
        mx0 = fmaxf(mx0, __shfl_xor_sync(0xffffffffu, mx0, 2));
        mx1 = fmaxf(mx1, __shfl_xor_sync(0xffffffffu, mx1, 1));
        mx1 = fmaxf(mx1, __shfl_xor_sync(0xffffffffu, mx1, 2));
        float mn0 = fmaxf(m2[0], mx0), mn1 = fmaxf(m2[1], mx1);
        float a0 = ex2f(m2[0] - mn0), a1 = ex2f(m2[1] - mn1);
        m2[0] = mn0; m2[1] = mn1;
        float ls0 = 0.f, ls1 = 0.f;
#pragma unroll
        for (int nf = 0; nf < 8; nf++) {
            float p0 = ex2f(s[nf][0] - mn0);
            float p1 = ex2f(s[nf][1] - mn0);
            float p2 = ex2f(s[nf][2] - mn1);
            float p3 = ex2f(s[nf][3] - mn1);
            s[nf][0] = p0; s[nf][1] = p1; s[nf][2] = p2; s[nf][3] = p3;
            ls0 += p0 + p1; ls1 += p2 + p3;
            O[nf][0] *= a0; O[nf][1] *= a0;
            O[nf][2] *= a1; O[nf][3] *= a1;
        }
        lsum[0] = lsum[0] * a0 + ls0;
        lsum[1] = lsum[1] * a1 + ls1;

#pragma unroll
        for (int kc = 0; kc < 4; kc++) {
            uint32_t ph[4], pl[4];
            split_pair(s[2 * kc][0],     s[2 * kc][1],     ph[0], pl[0]);
            split_pair(s[2 * kc][2],     s[2 * kc][3],     ph[1], pl[1]);
            split_pair(s[2 * kc + 1][0], s[2 * kc + 1][1], ph[2], pl[2]);
            split_pair(s[2 * kc + 1][2], s[2 * kc + 1][3], ph[3], pl[3]);
#pragma unroll
            for (int np = 0; np < 4; np++) {
                uint32_t vh[4], vl[4];
                const uint32_t va = kb + 2 * APLANE + vaddr_off +
                                    kc * 16 * ASTRIDE + np * 32;
                LDM4T(vh[0], vh[1], vh[2], vh[3], va);
                LDM4T(vl[0], vl[1], vl[2], vl[3], va + APLANE);
                mma_bf16(O[2 * np],     ph, vh);
                mma_bf16(O[2 * np],     pl, vh);
                mma_bf16(O[2 * np],     ph, vl);
                mma_bf16(O[2 * np + 1], ph, vh + 2);
                mma_bf16(O[2 * np + 1], pl, vh + 2);
                mma_bf16(O[2 * np + 1], ph, vl + 2);
            }
        }
    }

    float l0 = lsum[0];
    l0 += __shfl_xor_sync(0xffffffffu, l0, 1);
    l0 += __shfl_xor_sync(0xffffffffu, l0, 2);
    float l1 = lsum[1];
    l1 += __shfl_xor_sync(0xffffffffu, l1, 1);
    l1 += __shfl_xor_sync(0xffffffffu, l1, 2);
    const float inv0 = 1.f / l0, inv1 = 1.f / l1;

    const int b = bh >> 3;
    const int h = bh & 7;
    const int t0 = qt * 64 + wid * 16 + g;
    const size_t r0 = (size_t)b * TT + t0;
    const size_t r1 = r0 + 8;
#pragma unroll
    for (int nf = 0; nf < 8; nf++) {
        int col = h * HD + nf * 8 + 2 * q;
        __half2 p0 = __floats2half2_rn(O[nf][0] * inv0, O[nf][1] * inv0);
        __half2 p1 = __floats2half2_rn(O[nf][2] * inv1, O[nf][3] * inv1);
        *(uint32_t*)(g_ah + r0 * KDIM + col) = *(uint32_t*)&p0;
        *(uint32_t*)(g_ah + r1 * KDIM + col) = *(uint32_t*)&p1;
    }
}

// ---------------------------------------------------------------------------
extern "C" void kernel_launch(void* const* d_in, const int* in_sizes, int n_in,
                              void* d_out, int out_size)
{
    const float* x    = (const float*)d_in[0];
    const float* cosT = (const float*)d_in[1];
    const float* sinT = (const float*)d_in[2];
    const float* Wqkv = (const float*)d_in[3];
    const float* Wout = (const float*)d_in[4];
    float* out = (float*)d_out;

    cudaFuncSetAttribute(mma_gemm_kernel<0>,
                         cudaFuncAttributeMaxDynamicSharedMemorySize, SMEM_BYTES);
    cudaFuncSetAttribute(mma_gemm_kernel<1>,
                         cudaFuncAttributeMaxDynamicSharedMemorySize, SMEM_BYTES);
    cudaFuncSetAttribute(attn_mma_kernel,
                         cudaFuncAttributeMaxDynamicSharedMemorySize, ATT_SMEM);

    uint16_t *xh, *w1h, *w2h, *ah;
    cudaGetSymbolAddress((void**)&xh,  g_xh);
    cudaGetSymbolAddress((void**)&w1h, g_w1h);
    cudaGetSymbolAddress((void**)&w2h, g_w2h);
    cudaGetSymbolAddress((void**)&ah,  g_ah);

    {
        int n4 = (BB * TT * DD) / 4;
        cvt16_kernel<<<n4 / 256, 256>>>((const float4*)x, (uint2*)xh, n4);
        int w1 = (3 * DD * KDIM) / 4;
        cvt16_kernel<<<(w1 + 255) / 256, 256>>>((const float4*)Wqkv, (uint2*)w1h, w1);
        int w2 = (DD * KDIM) / 4;
        cvt16_kernel<<<(w2 + 255) / 256, 256>>>((const float4*)Wout, (uint2*)w2h, w2);
    }

    dim3 g1(12, 512);   // N=1536, M=65536
    mma_gemm_kernel<0><<<g1, 256, SMEM_BYTES>>>(xh, w1h, cosT, sinT, nullptr);

    dim3 ga(4, BB * HH);
    attn_mma_kernel<<<ga, 128, ATT_SMEM>>>();

    dim3 g2(4, 512);    // N=512
    mma_gemm_kernel<1><<<g2, 256, SMEM_BYTES>>>(ah, w2h, cosT, sinT, out);
}